// round 9
// baseline (speedup 1.0000x reference)
#include <cuda_runtime.h>
#include <math.h>
#include <stdlib.h>

#define BB 16
#define TT 2048
#define DD 256
#define MM 1024
#define KW 7
#define TKW (TT - 1 + KW)      /* 2054 */
#define PCONV (DD * KW)        /* 1792 */
#define NQ (BB * TT)           /* 32768 */
#define QELEMS (BB * TT * DD)  /* 8388608 */

namespace { struct HxEnv { HxEnv() { setenv("CUDA_MODULE_LOADING", "EAGER", 1); } }; static HxEnv hx_env_; }

__device__ int    g_counts[MM];
__device__ float  g_e2[MM];
__device__ double g_scalePart[BB][8];
__device__ float  g_coef1[BB];
__device__ float  g_cpow;
__device__ double g_commit;
__device__ double g_pred;

__device__ __forceinline__ float prelu(float z, float a) { return z >= 0.f ? z : a * z; }

#define GEMM16(Am, Bm, rsel, csel)                                            \
    _Pragma("unroll")                                                         \
    for (int p = 0; p < 16; p++) {                                            \
        float4 a0 = *(const float4*)&(Am)[p * 132 + (rsel) * 4];              \
        float4 a1 = *(const float4*)&(Am)[p * 132 + (rsel) * 4 + 64];         \
        float4 b0 = *(const float4*)&(Bm)[p * 132 + (csel) * 4];              \
        float4 b1 = *(const float4*)&(Bm)[p * 132 + (csel) * 4 + 64];         \
        float av[8] = {a0.x, a0.y, a0.z, a0.w, a1.x, a1.y, a1.z, a1.w};       \
        float bv[8] = {b0.x, b0.y, b0.z, b0.w, b1.x, b1.y, b1.z, b1.w};       \
        _Pragma("unroll")                                                     \
        for (int i_ = 0; i_ < 8; i_++)                                        \
            _Pragma("unroll")                                                 \
            for (int j_ = 0; j_ < 8; j_++) acc[i_][j_] += av[i_] * bv[j_];    \
    }

__global__ void k_init() {
    int n = blockIdx.x * blockDim.x + threadIdx.x;
    if (n < MM) g_counts[n] = 0;
    if (n == 0) { g_commit = 0.0; g_pred = 0.0; }
}

__global__ void k_e2(const float* __restrict__ emb) {
    int m = blockIdx.x * 256 + threadIdx.x;
    const float4* r = (const float4*)(emb + (size_t)m * DD);
    double s = 0.0;
#pragma unroll 8
    for (int j = 0; j < DD / 4; j++) {
        float4 v = r[j];
        s += (double)v.x * v.x + (double)v.y * v.y + (double)v.z * v.z + (double)v.w * v.w;
    }
    g_e2[m] = (float)s;
}

__global__ void k_scale1(const float* __restrict__ x) {
    const int NE = (TT - 1) * DD;
    int b = blockIdx.y;
    int per = NE / 8;
    int start = blockIdx.x * per;
    const float* xb = x + (size_t)b * TT * DD;
    double s = 0.0;
    for (int j = start + threadIdx.x; j < start + per; j += blockDim.x) { float v = xb[j]; s += (double)v * v; }
    __shared__ double sh[256];
    sh[threadIdx.x] = s; __syncthreads();
    for (int st = 128; st; st >>= 1) { if (threadIdx.x < st) sh[threadIdx.x] += sh[threadIdx.x + st]; __syncthreads(); }
    if (threadIdx.x == 0) g_scalePart[b][blockIdx.x] = sh[0];
}

__global__ void k_coef(const int* __restrict__ epoPtr) {
    int b = threadIdx.x;
    if (b >= BB) return;
    double ef = 5.0;
    if (epoPtr) {
        int raw = epoPtr[0];
        ef = (raw >= 0 && raw <= 100000) ? (double)raw : (double)__int_as_float(raw);
    }
    double s = 0.0;
    for (int j = 0; j < 8; j++) s += g_scalePart[b][j];
    double mean = s / (double)(DD * TKW);
    g_coef1[b] = (float)(0.5 * sqrt(mean));
    if (b == 0) g_cpow = (float)pow(0.5, ef * 0.1);
}

__global__ __launch_bounds__(256) void k_conv(const float* __restrict__ w, const float* __restrict__ noise,
                                              const float* __restrict__ x, float* __restrict__ dout) {
    __shared__ float As[16 * 132];
    __shared__ float Bs[16 * 132];
    int b = blockIdx.z, t0 = blockIdx.x * 128, o0 = blockIdx.y * 128;
    int tid = threadIdx.x;
    int rt = tid >> 4, ct = tid & 15;
    int la = tid & 15, lo = tid >> 4;
    int lt = tid & 127, lr = tid >> 7;
    float coef1 = g_coef1[b];
    float cpow = g_cpow;
    const float* nb = noise + (size_t)b * DD * TKW;
    const float* xb = x + (size_t)b * TT * DD;
    float acc[8][8] = {};
    for (int pc = 0; pc < PCONV; pc += 16) {
#pragma unroll
        for (int r = 0; r < 8; r++) {
            int o = lo + 16 * r;
            As[la * 132 + o] = w[(size_t)(o0 + o) * PCONV + pc + la];
        }
#pragma unroll
        for (int r = 0; r < 8; r++) {
            int p = lr + 2 * r;
            int pg = pc + p;
            int i = pg / 7, k = pg - 7 * i;
            int tau = t0 + lt + k;
            float v = (coef1 * nb[(size_t)i * TKW + tau]) * cpow;
            if (tau >= KW) v += xb[(size_t)(tau - KW) * DD + i];
            Bs[p * 132 + lt] = v;
        }
        __syncthreads();
        GEMM16(As, Bs, rt, ct)
        __syncthreads();
    }
#pragma unroll
    for (int in = 0; in < 8; in++) {
        int t = t0 + ct * 4 + (in >> 2) * 64 + (in & 3);
        float* row = dout + ((size_t)(b * TT) + t) * DD + o0;
        float4 v0 = {acc[0][in], acc[1][in], acc[2][in], acc[3][in]};
        float4 v1 = {acc[4][in], acc[5][in], acc[6][in], acc[7][in]};
        *(float4*)&row[rt * 4] = v0;
        *(float4*)&row[rt * 4 + 64] = v1;
    }
}

__device__ __forceinline__ unsigned long long vq_key(float v, int m) {
    unsigned u = __float_as_uint(v);
    u = (u & 0x80000000u) ? ~u : (u | 0x80000000u);
    return ((unsigned long long)u << 32) | (unsigned)m;
}
__device__ __forceinline__ float vq_val(unsigned long long k) {
    unsigned u = (unsigned)(k >> 32);
    u = (u & 0x80000000u) ? (u & 0x7fffffffu) : ~u;
    return __uint_as_float(u);
}

// Fused merge1 + VQ. Distance metric replicates the reference's fp32 rounding
// chain: dq = fl( fl(e2[m] + c2[n]) - 2*dot ). c2's value is arbitrary up to
// ulp-multiples (translation invariance of RN within a binade) -> my lattice
// == ref lattice + uniform shift -> identical argmin incl. lowest-index ties.
__global__ __launch_bounds__(256) void k_m1vq(const float* __restrict__ x, const float* __restrict__ emb,
                                              const float* __restrict__ w1, const float* __restrict__ a1,
                                              float* __restrict__ dout) {
    extern __shared__ float sm[];
    float* cx  = sm;                 // 256 x 132
    float* As  = sm + 256 * 132;     // 16 x 132
    float* Bs  = As + 16 * 132;      // 16 x 132
    float* e2s = Bs + 16 * 132;      // 128
    float* c2s = e2s + 128;          // 128
    int b = blockIdx.y, t0 = blockIdx.x * 128;
    int tid = threadIdx.x;
    int rt = tid >> 4, ct = tid & 15;
    int la = tid & 15, lo = tid >> 4;
    float alpha = a1[0];
    const size_t rowbase = (size_t)(b * TT) + t0;

    // ---- merge1: cur_x = PReLU(W1 * [x; ctx]) ----
    for (int oh = 0; oh < 2; oh++) {
        int o0 = oh * 128;
        float acc[8][8] = {};
        for (int pc = 0; pc < 2 * DD; pc += 16) {
#pragma unroll
            for (int r = 0; r < 8; r++) {
                int o = lo + 16 * r;
                As[la * 132 + o] = w1[(size_t)(o0 + o) * (2 * DD) + pc + la];
            }
#pragma unroll
            for (int h = 0; h < 2; h++) {
                int id2 = tid * 2 + h;
                int t = id2 >> 2;
                int qi = (id2 & 3) * 4;
                int i = pc + qi;
                const float* src = (i < DD) ? &x[(rowbase + t) * DD + i]
                                            : &dout[(rowbase + t) * DD + (i - DD)];
                float4 v = *(const float4*)src;
                Bs[(qi + 0) * 132 + t] = v.x;
                Bs[(qi + 1) * 132 + t] = v.y;
                Bs[(qi + 2) * 132 + t] = v.z;
                Bs[(qi + 3) * 132 + t] = v.w;
            }
            __syncthreads();
            GEMM16(As, Bs, rt, ct)
            __syncthreads();
        }
#pragma unroll
        for (int im = 0; im < 8; im++) {
            int o = o0 + rt * 4 + (im >> 2) * 64 + (im & 3);
            float4 v0 = {prelu(acc[im][0], alpha), prelu(acc[im][1], alpha), prelu(acc[im][2], alpha), prelu(acc[im][3], alpha)};
            float4 v1 = {prelu(acc[im][4], alpha), prelu(acc[im][5], alpha), prelu(acc[im][6], alpha), prelu(acc[im][7], alpha)};
            *(float4*)&cx[o * 132 + ct * 4] = v0;
            *(float4*)&cx[o * 132 + ct * 4 + 64] = v1;
        }
    }
    __syncthreads();

    // ---- c2[n] in fp32 (any order: ulp-multiple error is absorbed by invariance) ----
    if (tid < 128) {
        float c2 = 0.f;
        for (int o = 0; o < DD; o++) { float v = cx[o * 132 + tid]; c2 = fmaf(v, v, c2); }
        c2s[tid] = c2;
    }
    __syncthreads();

    // ---- VQ pass 1: top-2 by quantized-chain distance ----
    int cmt = tid & 15, cnt = tid >> 4;
    int dd_ = tid & 15, lm = tid >> 4;
    float myc2[8];
#pragma unroll
    for (int in = 0; in < 8; in++) myc2[in] = c2s[cnt * 4 + (in >> 2) * 64 + (in & 3)];
    unsigned long long b1[8], b2[8];
#pragma unroll
    for (int i = 0; i < 8; i++) { b1[i] = 0xFFFFFFFFFFFFFFFFull; b2[i] = 0xFFFFFFFFFFFFFFFFull; }
    for (int mt = 0; mt < 8; mt++) {
        int m0 = mt * 128;
        if (tid < 128) e2s[tid] = g_e2[m0 + tid];
        float acc[8][8] = {};
        for (int dc = 0; dc < DD; dc += 16) {
#pragma unroll
            for (int r = 0; r < 8; r++) {
                int m = lm + 16 * r;
                Bs[dd_ * 132 + m] = emb[(size_t)(m0 + m) * DD + dc + dd_];
            }
            __syncthreads();
            GEMM16(Bs, (&cx[dc * 132]), cmt, cnt)
            __syncthreads();
        }
#pragma unroll
        for (int in = 0; in < 8; in++) {
#pragma unroll
            for (int im = 0; im < 8; im++) {
                int ml = cmt * 4 + (im >> 2) * 64 + (im & 3);
                float t1 = e2s[ml] + myc2[in];          // fl(e2 + c2)
                float dq = t1 - 2.0f * acc[im][in];     // fl(t1 - 2*dot); 2*dot exact
                unsigned long long key = vq_key(dq, m0 + ml);
                if (key < b1[in]) { b2[in] = b1[in]; b1[in] = key; }
                else if (key < b2[in]) b2[in] = key;
            }
        }
        __syncthreads();
    }
#pragma unroll
    for (int in = 0; in < 8; in++) {
        unsigned long long k1 = b1[in], k2 = b2[in];
#pragma unroll
        for (int off = 8; off; off >>= 1) {
            unsigned long long o1 = __shfl_xor_sync(0xffffffffu, k1, off);
            unsigned long long o2 = __shfl_xor_sync(0xffffffffu, k2, off);
            unsigned long long lo = (k1 < o1) ? k1 : o1;
            unsigned long long hi = (k1 < o1) ? o1 : k1;
            unsigned long long m22 = (k2 < o2) ? k2 : o2;
            k2 = (hi < m22) ? hi : m22;
            k1 = lo;
        }
        if (cmt == 0) {
            int ncol = cnt * 4 + (in >> 2) * 64 + (in & 3);
            int m1 = (int)(k1 & 0xFFFFFFFFull);
            int m2 = (int)(k2 & 0xFFFFFFFFull);
            int mwin = m1;
            float v1 = vq_val(k1), v2 = vq_val(k2);
            if (v2 - v1 < 1e-4f) {
                // pass 2: fp64 dots (~ref dot +-1ulp) through the SAME fp32 chain
                double d1 = 0.0, d2 = 0.0;
                const float* e1 = emb + (size_t)m1 * DD;
                const float* e2p = emb + (size_t)m2 * DD;
                for (int o = 0; o < DD; o++) {
                    double c = (double)cx[o * 132 + ncol];
                    d1 += c * (double)e1[o];
                    d2 += c * (double)e2p[o];
                }
                float c2n = myc2[in];
                float q1 = (g_e2[m1] + c2n) - 2.0f * (float)d1;
                float q2 = (g_e2[m2] + c2n) - 2.0f * (float)d2;
                if (q2 < q1 || (q2 == q1 && m2 < m1)) mwin = m2;
            }
            int n = t0 + ncol;
            dout[QELEMS + (size_t)b * TT + n] = (float)mwin;
            atomicAdd(&g_counts[mwin], 1);
        }
    }
}

__global__ void k_loss(const float* __restrict__ x, const float* __restrict__ emb,
                       const float* __restrict__ dout) {
    int n = blockIdx.x * 8 + (threadIdx.x >> 5);
    int d0 = (threadIdx.x & 31) * 8;
    int m = (int)dout[QELEMS + n];
    size_t base = (size_t)n * DD + d0;
    size_t ebase = (size_t)m * DD + d0;
    float sc = 0.f, sp = 0.f;
#pragma unroll
    for (int h = 0; h < 2; h++) {
        float4 xv = *(const float4*)&x[base + h * 4];
        float4 cv = *(const float4*)&dout[base + h * 4];
        float4 qv = *(const float4*)&emb[ebase + h * 4];
        float d1, d2;
        d1 = xv.x - cv.x - qv.x; sc += d1 * d1; d2 = cv.x - xv.x; sp += d2 * d2;
        d1 = xv.y - cv.y - qv.y; sc += d1 * d1; d2 = cv.y - xv.y; sp += d2 * d2;
        d1 = xv.z - cv.z - qv.z; sc += d1 * d1; d2 = cv.z - xv.z; sp += d2 * d2;
        d1 = xv.w - cv.w - qv.w; sc += d1 * d1; d2 = cv.w - xv.w; sp += d2 * d2;
    }
    __shared__ double red[256];
    red[threadIdx.x] = (double)sc; __syncthreads();
    for (int st = 128; st; st >>= 1) { if (threadIdx.x < st) red[threadIdx.x] += red[threadIdx.x + st]; __syncthreads(); }
    if (threadIdx.x == 0) atomicAdd(&g_commit, red[0]);
    __syncthreads();
    red[threadIdx.x] = (double)sp; __syncthreads();
    for (int st = 128; st; st >>= 1) { if (threadIdx.x < st) red[threadIdx.x] += red[threadIdx.x + st]; __syncthreads(); }
    if (threadIdx.x == 0) atomicAdd(&g_pred, red[0]);
}

__global__ __launch_bounds__(256) void k_merge2(const float* __restrict__ emb, const float* __restrict__ w2,
                                                const float* __restrict__ a2, float* __restrict__ dout) {
    extern __shared__ float sm[];
    float* ctxs = sm;                // 256 x 132
    float* As   = sm + 256 * 132;
    float* Bs   = As + 16 * 132;
    int*   idxs = (int*)(Bs + 16 * 132);
    int b = blockIdx.y, t0 = blockIdx.x * 128;
    int tid = threadIdx.x;
    int rt = tid >> 4, ct = tid & 15;
    int la = tid & 15, lo = tid >> 4;
    float alpha = a2[0];
    const size_t rowbase = (size_t)(b * TT) + t0;

    for (int k2 = 0; k2 < 32; k2++) {
        int id4 = k2 * 256 + tid;
        int t = id4 >> 6;
        int q = id4 & 63;
        float4 v = *(const float4*)&dout[(rowbase + t) * DD + q * 4];
        ctxs[(q * 4 + 0) * 132 + t] = v.x;
        ctxs[(q * 4 + 1) * 132 + t] = v.y;
        ctxs[(q * 4 + 2) * 132 + t] = v.z;
        ctxs[(q * 4 + 3) * 132 + t] = v.w;
    }
    if (tid < 128) idxs[tid] = (int)dout[QELEMS + (size_t)b * TT + t0 + tid];
    __syncthreads();

    for (int oh = 0; oh < 2; oh++) {
        int o0 = oh * 128;
        float acc[8][8] = {};
        for (int pc = 0; pc < 2 * DD; pc += 16) {
#pragma unroll
            for (int r = 0; r < 8; r++) {
                int o = lo + 16 * r;
                As[la * 132 + o] = w2[(size_t)(o0 + o) * (2 * DD) + pc + la];
            }
            if (pc < DD) {
#pragma unroll
                for (int h = 0; h < 2; h++) {
                    int id2 = tid * 2 + h;
                    int t = id2 >> 2;
                    int qi = (id2 & 3) * 4;
                    float4 v = *(const float4*)&emb[(size_t)idxs[t] * DD + pc + qi];
                    Bs[(qi + 0) * 132 + t] = v.x;
                    Bs[(qi + 1) * 132 + t] = v.y;
                    Bs[(qi + 2) * 132 + t] = v.z;
                    Bs[(qi + 3) * 132 + t] = v.w;
                }
                __syncthreads();
                GEMM16(As, Bs, rt, ct)
                __syncthreads();
            } else {
                __syncthreads();
                GEMM16(As, (&ctxs[(pc - DD) * 132]), rt, ct)
                __syncthreads();
            }
        }
#pragma unroll
        for (int in = 0; in < 8; in++) {
            int t = t0 + ct * 4 + (in >> 2) * 64 + (in & 3);
            float* row = dout + ((size_t)(b * TT) + t) * DD + o0;
            float4 v0 = {prelu(acc[0][in], alpha), prelu(acc[1][in], alpha), prelu(acc[2][in], alpha), prelu(acc[3][in], alpha)};
            float4 v1 = {prelu(acc[4][in], alpha), prelu(acc[5][in], alpha), prelu(acc[6][in], alpha), prelu(acc[7][in], alpha)};
            *(float4*)&row[rt * 4] = v0;
            *(float4*)&row[rt * 4 + 64] = v1;
        }
    }
}

__global__ void k_stats(float* __restrict__ dout) {
    __shared__ float sUsed[1024];
    __shared__ float sEnt[1024];
    int m = threadIdx.x;
    float c = (float)g_counts[m];
    sUsed[m] = (c >= 1.0f) ? 1.0f : 0.0f;
    float p = c / (float)NQ;
    sEnt[m] = p * logf(p + 1e-10f);
    __syncthreads();
    for (int st = 512; st; st >>= 1) {
        if (m < st) { sUsed[m] += sUsed[m + st]; sEnt[m] += sEnt[m + st]; }
        __syncthreads();
    }
    if (m == 0) {
        dout[QELEMS + NQ + 0] = sUsed[0];
        dout[QELEMS + NQ + 1] = expf(-sEnt[0]);
        dout[QELEMS + NQ + 2] = (float)(g_commit / (double)QELEMS);
        dout[QELEMS + NQ + 3] = (float)(g_pred / (double)QELEMS);
    }
}

extern "C" void kernel_launch(void* const* d_in, const int* in_sizes, int n_in,
                              void* d_out, int out_size) {
    const float* x     = (const float*)d_in[0];
    const float* emb   = (const float*)d_in[1];
    const float* w_ctx = (const float*)d_in[2];
    const float* w1    = (const float*)d_in[3];
    const float* a1    = (const float*)d_in[4];
    const float* w2    = (const float*)d_in[5];
    const float* a2    = (const float*)d_in[6];
    const float* noise = (const float*)d_in[7];
    const int*   epo   = (n_in > 8) ? (const int*)d_in[8] : nullptr;
    float* dout = (float*)d_out;

    const int SMEM_DYN = (256 * 132 + 2 * 16 * 132 + 384) * 4;   // 153,600 B
    cudaFuncSetAttribute(k_m1vq,   cudaFuncAttributeMaxDynamicSharedMemorySize, SMEM_DYN);
    cudaFuncSetAttribute(k_merge2, cudaFuncAttributeMaxDynamicSharedMemorySize, SMEM_DYN);

    k_init<<<4, 256>>>();
    k_e2<<<MM / 256, 256>>>(emb);
    k_scale1<<<dim3(8, BB), 256>>>(x);
    k_coef<<<1, 32>>>(epo);
    k_conv<<<dim3(TT / 128, DD / 128, BB), 256>>>(w_ctx, noise, x, dout);
    k_m1vq<<<dim3(TT / 128, BB), 256, SMEM_DYN>>>(x, emb, w1, a1, dout);
    k_loss<<<NQ / 8, 256>>>(x, emb, dout);
    k_merge2<<<dim3(TT / 128, BB), 256, SMEM_DYN>>>(emb, w2, a2, dout);
    k_stats<<<1, 1024>>>(dout);
    (void)in_sizes; (void)out_size;
}

// round 10
// speedup vs baseline: 1.1229x; 1.1229x over previous
#include <cuda_runtime.h>
#include <math.h>
#include <stdlib.h>

#define BB 16
#define TT 2048
#define DD 256
#define MM 1024
#define KW 7
#define TKW (TT - 1 + KW)      /* 2054 */
#define PCONV (DD * KW)        /* 1792 */
#define NQ (BB * TT)           /* 32768 */
#define QELEMS (BB * TT * DD)  /* 8388608 */

namespace { struct HxEnv { HxEnv() { setenv("CUDA_MODULE_LOADING", "EAGER", 1); } }; static HxEnv hx_env_; }

__device__ int    g_counts[MM];
__device__ float  g_e2[MM];
__device__ double g_scalePart[BB][8];
__device__ float  g_coef1[BB];
__device__ float  g_cpow;
__device__ double g_commit;
__device__ double g_pred;

__device__ __forceinline__ float prelu(float z, float a) { return z >= 0.f ? z : a * z; }

// ---- 128x128x16 GEMM inner product using packed fma.rn.f32x2.
// Bit-exact vs the scalar version: each accumulator lane is an independent
// IEEE-RN FMA chain in the identical p-order; two chains share one issue slot.
// acc2[i][j] packs t-columns (2j, 2j+1) in (lo, hi) 32-bit halves.
#define GEMM16(Am, Bm, rsel, csel)                                            \
    _Pragma("unroll")                                                         \
    for (int p = 0; p < 16; p++) {                                            \
        float4 a0 = *(const float4*)&(Am)[p * 132 + (rsel) * 4];              \
        float4 a1 = *(const float4*)&(Am)[p * 132 + (rsel) * 4 + 64];         \
        ulonglong2 bq0 = *(const ulonglong2*)&(Bm)[p * 132 + (csel) * 4];     \
        ulonglong2 bq1 = *(const ulonglong2*)&(Bm)[p * 132 + (csel) * 4 + 64];\
        float av[8] = {a0.x, a0.y, a0.z, a0.w, a1.x, a1.y, a1.z, a1.w};       \
        unsigned long long bv2[4] = {bq0.x, bq0.y, bq1.x, bq1.y};             \
        _Pragma("unroll")                                                     \
        for (int i_ = 0; i_ < 8; i_++) {                                      \
            unsigned long long a2_;                                           \
            asm("mov.b64 %0, {%1, %1};" : "=l"(a2_) : "f"(av[i_]));           \
            _Pragma("unroll")                                                 \
            for (int j_ = 0; j_ < 4; j_++)                                    \
                asm("fma.rn.f32x2 %0, %1, %2, %0;"                            \
                    : "+l"(acc2[i_][j_]) : "l"(a2_), "l"(bv2[j_]));           \
        }                                                                     \
    }

// Accessor: acc[i][j] of the old scalar layout.
#define ACCF(i_, j_) \
    __uint_as_float((unsigned)(((j_) & 1) ? (acc2[(i_)][(j_) >> 1] >> 32) : acc2[(i_)][(j_) >> 1]))

__global__ void k_init() {
    int n = blockIdx.x * blockDim.x + threadIdx.x;
    if (n < MM) g_counts[n] = 0;
    if (n == 0) { g_commit = 0.0; g_pred = 0.0; }
}

__global__ void k_e2(const float* __restrict__ emb) {
    int m = blockIdx.x * 256 + threadIdx.x;
    const float4* r = (const float4*)(emb + (size_t)m * DD);
    double s = 0.0;
#pragma unroll 8
    for (int j = 0; j < DD / 4; j++) {
        float4 v = r[j];
        s += (double)v.x * v.x + (double)v.y * v.y + (double)v.z * v.z + (double)v.w * v.w;
    }
    g_e2[m] = (float)s;
}

__global__ void k_scale1(const float* __restrict__ x) {
    const int NE = (TT - 1) * DD;
    int b = blockIdx.y;
    int per = NE / 8;
    int start = blockIdx.x * per;
    const float* xb = x + (size_t)b * TT * DD;
    double s = 0.0;
    for (int j = start + threadIdx.x; j < start + per; j += blockDim.x) { float v = xb[j]; s += (double)v * v; }
    __shared__ double sh[256];
    sh[threadIdx.x] = s; __syncthreads();
    for (int st = 128; st; st >>= 1) { if (threadIdx.x < st) sh[threadIdx.x] += sh[threadIdx.x + st]; __syncthreads(); }
    if (threadIdx.x == 0) g_scalePart[b][blockIdx.x] = sh[0];
}

__global__ void k_coef(const int* __restrict__ epoPtr) {
    int b = threadIdx.x;
    if (b >= BB) return;
    double ef = 5.0;
    if (epoPtr) {
        int raw = epoPtr[0];
        ef = (raw >= 0 && raw <= 100000) ? (double)raw : (double)__int_as_float(raw);
    }
    double s = 0.0;
    for (int j = 0; j < 8; j++) s += g_scalePart[b][j];
    double mean = s / (double)(DD * TKW);
    g_coef1[b] = (float)(0.5 * sqrt(mean));
    if (b == 0) g_cpow = (float)pow(0.5, ef * 0.1);
}

__global__ __launch_bounds__(256) void k_conv(const float* __restrict__ w, const float* __restrict__ noise,
                                              const float* __restrict__ x, float* __restrict__ dout) {
    __shared__ float As[16 * 132];
    __shared__ float Bs[16 * 132];
    int b = blockIdx.z, t0 = blockIdx.x * 128, o0 = blockIdx.y * 128;
    int tid = threadIdx.x;
    int rt = tid >> 4, ct = tid & 15;
    int la = tid & 15, lo = tid >> 4;
    int lt = tid & 127, lr = tid >> 7;
    float coef1 = g_coef1[b];
    float cpow = g_cpow;
    const float* nb = noise + (size_t)b * DD * TKW;
    const float* xb = x + (size_t)b * TT * DD;
    unsigned long long acc2[8][4] = {};
    for (int pc = 0; pc < PCONV; pc += 16) {
#pragma unroll
        for (int r = 0; r < 8; r++) {
            int o = lo + 16 * r;
            As[la * 132 + o] = w[(size_t)(o0 + o) * PCONV + pc + la];
        }
#pragma unroll
        for (int r = 0; r < 8; r++) {
            int p = lr + 2 * r;
            int pg = pc + p;
            int i = pg / 7, k = pg - 7 * i;
            int tau = t0 + lt + k;
            float v = (coef1 * nb[(size_t)i * TKW + tau]) * cpow;
            if (tau >= KW) v += xb[(size_t)(tau - KW) * DD + i];
            Bs[p * 132 + lt] = v;
        }
        __syncthreads();
        GEMM16(As, Bs, rt, ct)
        __syncthreads();
    }
#pragma unroll
    for (int in = 0; in < 8; in++) {
        int t = t0 + ct * 4 + (in >> 2) * 64 + (in & 3);
        float* row = dout + ((size_t)(b * TT) + t) * DD + o0;
        float4 v0 = {ACCF(0, in), ACCF(1, in), ACCF(2, in), ACCF(3, in)};
        float4 v1 = {ACCF(4, in), ACCF(5, in), ACCF(6, in), ACCF(7, in)};
        *(float4*)&row[rt * 4] = v0;
        *(float4*)&row[rt * 4 + 64] = v1;
    }
}

__device__ __forceinline__ unsigned long long vq_key(float v, int m) {
    unsigned u = __float_as_uint(v);
    u = (u & 0x80000000u) ? ~u : (u | 0x80000000u);
    return ((unsigned long long)u << 32) | (unsigned)m;
}
__device__ __forceinline__ float vq_val(unsigned long long k) {
    unsigned u = (unsigned)(k >> 32);
    u = (u & 0x80000000u) ? (u & 0x7fffffffu) : ~u;
    return __uint_as_float(u);
}

// Fused merge1 + VQ. Distance metric replicates the reference's fp32 rounding
// chain: dq = fl( fl(e2[m] + c2[n]) - 2*dot ).
__global__ __launch_bounds__(256) void k_m1vq(const float* __restrict__ x, const float* __restrict__ emb,
                                              const float* __restrict__ w1, const float* __restrict__ a1,
                                              float* __restrict__ dout) {
    extern __shared__ float sm[];
    float* cx  = sm;                 // 256 x 132
    float* As  = sm + 256 * 132;     // 16 x 132
    float* Bs  = As + 16 * 132;      // 16 x 132
    float* e2s = Bs + 16 * 132;      // 128
    float* c2s = e2s + 128;          // 128
    int b = blockIdx.y, t0 = blockIdx.x * 128;
    int tid = threadIdx.x;
    int rt = tid >> 4, ct = tid & 15;
    int la = tid & 15, lo = tid >> 4;
    float alpha = a1[0];
    const size_t rowbase = (size_t)(b * TT) + t0;

    // ---- merge1: cur_x = PReLU(W1 * [x; ctx]) ----
    for (int oh = 0; oh < 2; oh++) {
        int o0 = oh * 128;
        unsigned long long acc2[8][4] = {};
        for (int pc = 0; pc < 2 * DD; pc += 16) {
#pragma unroll
            for (int r = 0; r < 8; r++) {
                int o = lo + 16 * r;
                As[la * 132 + o] = w1[(size_t)(o0 + o) * (2 * DD) + pc + la];
            }
#pragma unroll
            for (int h = 0; h < 2; h++) {
                int id2 = tid * 2 + h;
                int t = id2 >> 2;
                int qi = (id2 & 3) * 4;
                int i = pc + qi;
                const float* src = (i < DD) ? &x[(rowbase + t) * DD + i]
                                            : &dout[(rowbase + t) * DD + (i - DD)];
                float4 v = *(const float4*)src;
                Bs[(qi + 0) * 132 + t] = v.x;
                Bs[(qi + 1) * 132 + t] = v.y;
                Bs[(qi + 2) * 132 + t] = v.z;
                Bs[(qi + 3) * 132 + t] = v.w;
            }
            __syncthreads();
            GEMM16(As, Bs, rt, ct)
            __syncthreads();
        }
#pragma unroll
        for (int im = 0; im < 8; im++) {
            int o = o0 + rt * 4 + (im >> 2) * 64 + (im & 3);
            float4 v0 = {prelu(ACCF(im, 0), alpha), prelu(ACCF(im, 1), alpha), prelu(ACCF(im, 2), alpha), prelu(ACCF(im, 3), alpha)};
            float4 v1 = {prelu(ACCF(im, 4), alpha), prelu(ACCF(im, 5), alpha), prelu(ACCF(im, 6), alpha), prelu(ACCF(im, 7), alpha)};
            *(float4*)&cx[o * 132 + ct * 4] = v0;
            *(float4*)&cx[o * 132 + ct * 4 + 64] = v1;
        }
    }
    __syncthreads();

    // ---- c2[n] in fp32 (value arbitrary up to small shifts; e2 term ~vanishes) ----
    if (tid < 128) {
        float c2 = 0.f;
        for (int o = 0; o < DD; o++) { float v = cx[o * 132 + tid]; c2 = fmaf(v, v, c2); }
        c2s[tid] = c2;
    }
    __syncthreads();

    // ---- VQ pass 1: top-2 by quantized-chain distance ----
    int cmt = tid & 15, cnt = tid >> 4;
    int dd_ = tid & 15, lm = tid >> 4;
    float myc2[8];
#pragma unroll
    for (int in = 0; in < 8; in++) myc2[in] = c2s[cnt * 4 + (in >> 2) * 64 + (in & 3)];
    unsigned long long b1[8], b2[8];
#pragma unroll
    for (int i = 0; i < 8; i++) { b1[i] = 0xFFFFFFFFFFFFFFFFull; b2[i] = 0xFFFFFFFFFFFFFFFFull; }
    for (int mt = 0; mt < 8; mt++) {
        int m0 = mt * 128;
        if (tid < 128) e2s[tid] = g_e2[m0 + tid];
        unsigned long long acc2[8][4] = {};
        for (int dc = 0; dc < DD; dc += 16) {
#pragma unroll
            for (int r = 0; r < 8; r++) {
                int m = lm + 16 * r;
                Bs[dd_ * 132 + m] = emb[(size_t)(m0 + m) * DD + dc + dd_];
            }
            __syncthreads();
            GEMM16(Bs, (&cx[dc * 132]), cmt, cnt)
            __syncthreads();
        }
#pragma unroll
        for (int in = 0; in < 8; in++) {
#pragma unroll
            for (int im = 0; im < 8; im++) {
                int ml = cmt * 4 + (im >> 2) * 64 + (im & 3);
                float t1 = e2s[ml] + myc2[in];          // fl(e2 + c2)
                float dq = t1 - 2.0f * ACCF(im, in);    // fl(t1 - 2*dot)
                unsigned long long key = vq_key(dq, m0 + ml);
                if (key < b1[in]) { b2[in] = b1[in]; b1[in] = key; }
                else if (key < b2[in]) b2[in] = key;
            }
        }
        __syncthreads();
    }
#pragma unroll
    for (int in = 0; in < 8; in++) {
        unsigned long long k1 = b1[in], k2 = b2[in];
#pragma unroll
        for (int off = 8; off; off >>= 1) {
            unsigned long long o1 = __shfl_xor_sync(0xffffffffu, k1, off);
            unsigned long long o2 = __shfl_xor_sync(0xffffffffu, k2, off);
            unsigned long long lo = (k1 < o1) ? k1 : o1;
            unsigned long long hi = (k1 < o1) ? o1 : k1;
            unsigned long long m22 = (k2 < o2) ? k2 : o2;
            k2 = (hi < m22) ? hi : m22;
            k1 = lo;
        }
        if (cmt == 0) {
            int ncol = cnt * 4 + (in >> 2) * 64 + (in & 3);
            int m1 = (int)(k1 & 0xFFFFFFFFull);
            int m2 = (int)(k2 & 0xFFFFFFFFull);
            int mwin = m1;
            float v1 = vq_val(k1), v2 = vq_val(k2);
            if (v2 - v1 < 1e-4f) {
                double d1 = 0.0, d2 = 0.0;
                const float* e1 = emb + (size_t)m1 * DD;
                const float* e2p = emb + (size_t)m2 * DD;
                for (int o = 0; o < DD; o++) {
                    double c = (double)cx[o * 132 + ncol];
                    d1 += c * (double)e1[o];
                    d2 += c * (double)e2p[o];
                }
                float c2n = myc2[in];
                float q1 = (g_e2[m1] + c2n) - 2.0f * (float)d1;
                float q2 = (g_e2[m2] + c2n) - 2.0f * (float)d2;
                if (q2 < q1 || (q2 == q1 && m2 < m1)) mwin = m2;
            }
            int n = t0 + ncol;
            dout[QELEMS + (size_t)b * TT + n] = (float)mwin;
            atomicAdd(&g_counts[mwin], 1);
        }
    }
}

__global__ void k_loss(const float* __restrict__ x, const float* __restrict__ emb,
                       const float* __restrict__ dout) {
    int n = blockIdx.x * 8 + (threadIdx.x >> 5);
    int d0 = (threadIdx.x & 31) * 8;
    int m = (int)dout[QELEMS + n];
    size_t base = (size_t)n * DD + d0;
    size_t ebase = (size_t)m * DD + d0;
    float sc = 0.f, sp = 0.f;
#pragma unroll
    for (int h = 0; h < 2; h++) {
        float4 xv = *(const float4*)&x[base + h * 4];
        float4 cv = *(const float4*)&dout[base + h * 4];
        float4 qv = *(const float4*)&emb[ebase + h * 4];
        float d1, d2;
        d1 = xv.x - cv.x - qv.x; sc += d1 * d1; d2 = cv.x - xv.x; sp += d2 * d2;
        d1 = xv.y - cv.y - qv.y; sc += d1 * d1; d2 = cv.y - xv.y; sp += d2 * d2;
        d1 = xv.z - cv.z - qv.z; sc += d1 * d1; d2 = cv.z - xv.z; sp += d2 * d2;
        d1 = xv.w - cv.w - qv.w; sc += d1 * d1; d2 = cv.w - xv.w; sp += d2 * d2;
    }
    __shared__ double red[256];
    red[threadIdx.x] = (double)sc; __syncthreads();
    for (int st = 128; st; st >>= 1) { if (threadIdx.x < st) red[threadIdx.x] += red[threadIdx.x + st]; __syncthreads(); }
    if (threadIdx.x == 0) atomicAdd(&g_commit, red[0]);
    __syncthreads();
    red[threadIdx.x] = (double)sp; __syncthreads();
    for (int st = 128; st; st >>= 1) { if (threadIdx.x < st) red[threadIdx.x] += red[threadIdx.x + st]; __syncthreads(); }
    if (threadIdx.x == 0) atomicAdd(&g_pred, red[0]);
}

__global__ __launch_bounds__(256) void k_merge2(const float* __restrict__ emb, const float* __restrict__ w2,
                                                const float* __restrict__ a2, float* __restrict__ dout) {
    extern __shared__ float sm[];
    float* ctxs = sm;                // 256 x 132
    float* As   = sm + 256 * 132;
    float* Bs   = As + 16 * 132;
    int*   idxs = (int*)(Bs + 16 * 132);
    int b = blockIdx.y, t0 = blockIdx.x * 128;
    int tid = threadIdx.x;
    int rt = tid >> 4, ct = tid & 15;
    int la = tid & 15, lo = tid >> 4;
    float alpha = a2[0];
    const size_t rowbase = (size_t)(b * TT) + t0;

    for (int k2 = 0; k2 < 32; k2++) {
        int id4 = k2 * 256 + tid;
        int t = id4 >> 6;
        int q = id4 & 63;
        float4 v = *(const float4*)&dout[(rowbase + t) * DD + q * 4];
        ctxs[(q * 4 + 0) * 132 + t] = v.x;
        ctxs[(q * 4 + 1) * 132 + t] = v.y;
        ctxs[(q * 4 + 2) * 132 + t] = v.z;
        ctxs[(q * 4 + 3) * 132 + t] = v.w;
    }
    if (tid < 128) idxs[tid] = (int)dout[QELEMS + (size_t)b * TT + t0 + tid];
    __syncthreads();

    for (int oh = 0; oh < 2; oh++) {
        int o0 = oh * 128;
        unsigned long long acc2[8][4] = {};
        for (int pc = 0; pc < 2 * DD; pc += 16) {
#pragma unroll
            for (int r = 0; r < 8; r++) {
                int o = lo + 16 * r;
                As[la * 132 + o] = w2[(size_t)(o0 + o) * (2 * DD) + pc + la];
            }
            if (pc < DD) {
#pragma unroll
                for (int h = 0; h < 2; h++) {
                    int id2 = tid * 2 + h;
                    int t = id2 >> 2;
                    int qi = (id2 & 3) * 4;
                    float4 v = *(const float4*)&emb[(size_t)idxs[t] * DD + pc + qi];
                    Bs[(qi + 0) * 132 + t] = v.x;
                    Bs[(qi + 1) * 132 + t] = v.y;
                    Bs[(qi + 2) * 132 + t] = v.z;
                    Bs[(qi + 3) * 132 + t] = v.w;
                }
                __syncthreads();
                GEMM16(As, Bs, rt, ct)
                __syncthreads();
            } else {
                __syncthreads();
                GEMM16(As, (&ctxs[(pc - DD) * 132]), rt, ct)
                __syncthreads();
            }
        }
#pragma unroll
        for (int in = 0; in < 8; in++) {
            int t = t0 + ct * 4 + (in >> 2) * 64 + (in & 3);
            float* row = dout + ((size_t)(b * TT) + t) * DD + o0;
            float4 v0 = {prelu(ACCF(0, in), alpha), prelu(ACCF(1, in), alpha), prelu(ACCF(2, in), alpha), prelu(ACCF(3, in), alpha)};
            float4 v1 = {prelu(ACCF(4, in), alpha), prelu(ACCF(5, in), alpha), prelu(ACCF(6, in), alpha), prelu(ACCF(7, in), alpha)};
            *(float4*)&row[rt * 4] = v0;
            *(float4*)&row[rt * 4 + 64] = v1;
        }
    }
}

__global__ void k_stats(float* __restrict__ dout) {
    __shared__ float sUsed[1024];
    __shared__ float sEnt[1024];
    int m = threadIdx.x;
    float c = (float)g_counts[m];
    sUsed[m] = (c >= 1.0f) ? 1.0f : 0.0f;
    float p = c / (float)NQ;
    sEnt[m] = p * logf(p + 1e-10f);
    __syncthreads();
    for (int st = 512; st; st >>= 1) {
        if (m < st) { sUsed[m] += sUsed[m + st]; sEnt[m] += sEnt[m + st]; }
        __syncthreads();
    }
    if (m == 0) {
        dout[QELEMS + NQ + 0] = sUsed[0];
        dout[QELEMS + NQ + 1] = expf(-sEnt[0]);
        dout[QELEMS + NQ + 2] = (float)(g_commit / (double)QELEMS);
        dout[QELEMS + NQ + 3] = (float)(g_pred / (double)QELEMS);
    }
}

extern "C" void kernel_launch(void* const* d_in, const int* in_sizes, int n_in,
                              void* d_out, int out_size) {
    const float* x     = (const float*)d_in[0];
    const float* emb   = (const float*)d_in[1];
    const float* w_ctx = (const float*)d_in[2];
    const float* w1    = (const float*)d_in[3];
    const float* a1    = (const float*)d_in[4];
    const float* w2    = (const float*)d_in[5];
    const float* a2    = (const float*)d_in[6];
    const float* noise = (const float*)d_in[7];
    const int*   epo   = (n_in > 8) ? (const int*)d_in[8] : nullptr;
    float* dout = (float*)d_out;

    const int SMEM_DYN = (256 * 132 + 2 * 16 * 132 + 384) * 4;   // 153,600 B
    cudaFuncSetAttribute(k_m1vq,   cudaFuncAttributeMaxDynamicSharedMemorySize, SMEM_DYN);
    cudaFuncSetAttribute(k_merge2, cudaFuncAttributeMaxDynamicSharedMemorySize, SMEM_DYN);

    k_init<<<4, 256>>>();
    k_e2<<<MM / 256, 256>>>(emb);
    k_scale1<<<dim3(8, BB), 256>>>(x);
    k_coef<<<1, 32>>>(epo);
    k_conv<<<dim3(TT / 128, DD / 128, BB), 256>>>(w_ctx, noise, x, dout);
    k_m1vq<<<dim3(TT / 128, BB), 256, SMEM_DYN>>>(x, emb, w1, a1, dout);
    k_loss<<<NQ / 8, 256>>>(x, emb, dout);
    k_merge2<<<dim3(TT / 128, BB), 256, SMEM_DYN>>>(emb, w2, a2, dout);
    k_stats<<<1, 1024>>>(dout);
    (void)in_sizes; (void)out_size;
}

// round 11
// speedup vs baseline: 1.1267x; 1.0034x over previous
#include <cuda_runtime.h>
#include <math.h>
#include <stdlib.h>

#define BB 16
#define TT 2048
#define DD 256
#define MM 1024
#define KW 7
#define TKW (TT - 1 + KW)      /* 2054 */
#define PCONV (DD * KW)        /* 1792 */
#define NQ (BB * TT)           /* 32768 */
#define QELEMS (BB * TT * DD)  /* 8388608 */

namespace { struct HxEnv { HxEnv() { setenv("CUDA_MODULE_LOADING", "EAGER", 1); } }; static HxEnv hx_env_; }

__device__ int    g_counts[MM];
__device__ float  g_e2[MM];
__device__ double g_scalePart[BB][8];
__device__ float  g_coef1[BB];
__device__ float  g_cpow;
__device__ double g_commit;
__device__ double g_pred;

__device__ __forceinline__ float prelu(float z, float a) { return z >= 0.f ? z : a * z; }

// ---- 128x128x16 GEMM inner product, packed fma.rn.f32x2 (bit-exact per-lane RN chains).
#define GEMM16(Am, Bm, rsel, csel)                                            \
    _Pragma("unroll")                                                         \
    for (int p = 0; p < 16; p++) {                                            \
        float4 a0 = *(const float4*)&(Am)[p * 132 + (rsel) * 4];              \
        float4 a1 = *(const float4*)&(Am)[p * 132 + (rsel) * 4 + 64];         \
        ulonglong2 bq0 = *(const ulonglong2*)&(Bm)[p * 132 + (csel) * 4];     \
        ulonglong2 bq1 = *(const ulonglong2*)&(Bm)[p * 132 + (csel) * 4 + 64];\
        float av[8] = {a0.x, a0.y, a0.z, a0.w, a1.x, a1.y, a1.z, a1.w};       \
        unsigned long long bv2[4] = {bq0.x, bq0.y, bq1.x, bq1.y};             \
        _Pragma("unroll")                                                     \
        for (int i_ = 0; i_ < 8; i_++) {                                      \
            unsigned long long a2_;                                           \
            asm("mov.b64 %0, {%1, %1};" : "=l"(a2_) : "f"(av[i_]));           \
            _Pragma("unroll")                                                 \
            for (int j_ = 0; j_ < 4; j_++)                                    \
                asm("fma.rn.f32x2 %0, %1, %2, %0;"                            \
                    : "+l"(acc2[i_][j_]) : "l"(a2_), "l"(bv2[j_]));           \
        }                                                                     \
    }

#define ACCF(i_, j_) \
    __uint_as_float((unsigned)(((j_) & 1) ? (acc2[(i_)][(j_) >> 1] >> 32) : acc2[(i_)][(j_) >> 1]))

#define ACC_ZERO() do { _Pragma("unroll") for (int i_ = 0; i_ < 8; i_++) \
    _Pragma("unroll") for (int j_ = 0; j_ < 4; j_++) acc2[i_][j_] = 0ull; } while (0)

__global__ void k_init() {
    int n = blockIdx.x * blockDim.x + threadIdx.x;
    if (n < MM) g_counts[n] = 0;
    if (n == 0) { g_commit = 0.0; g_pred = 0.0; }
}

__global__ void k_e2(const float* __restrict__ emb) {
    int m = blockIdx.x * 256 + threadIdx.x;
    const float4* r = (const float4*)(emb + (size_t)m * DD);
    double s = 0.0;
#pragma unroll 8
    for (int j = 0; j < DD / 4; j++) {
        float4 v = r[j];
        s += (double)v.x * v.x + (double)v.y * v.y + (double)v.z * v.z + (double)v.w * v.w;
    }
    g_e2[m] = (float)s;
}

__global__ void k_scale1(const float* __restrict__ x) {
    const int NE = (TT - 1) * DD;
    int b = blockIdx.y;
    int per = NE / 8;
    int start = blockIdx.x * per;
    const float* xb = x + (size_t)b * TT * DD;
    double s = 0.0;
    for (int j = start + threadIdx.x; j < start + per; j += blockDim.x) { float v = xb[j]; s += (double)v * v; }
    __shared__ double sh[256];
    sh[threadIdx.x] = s; __syncthreads();
    for (int st = 128; st; st >>= 1) { if (threadIdx.x < st) sh[threadIdx.x] += sh[threadIdx.x + st]; __syncthreads(); }
    if (threadIdx.x == 0) g_scalePart[b][blockIdx.x] = sh[0];
}

__global__ void k_coef(const int* __restrict__ epoPtr) {
    int b = threadIdx.x;
    if (b >= BB) return;
    double ef = 5.0;
    if (epoPtr) {
        int raw = epoPtr[0];
        ef = (raw >= 0 && raw <= 100000) ? (double)raw : (double)__int_as_float(raw);
    }
    double s = 0.0;
    for (int j = 0; j < 8; j++) s += g_scalePart[b][j];
    double mean = s / (double)(DD * TKW);
    g_coef1[b] = (float)(0.5 * sqrt(mean));
    if (b == 0) g_cpow = (float)pow(0.5, ef * 0.1);
}

// ctx conv as GEMM, double-buffered smem pipeline.
__global__ __launch_bounds__(256) void k_conv(const float* __restrict__ w, const float* __restrict__ noise,
                                              const float* __restrict__ x, float* __restrict__ dout) {
    __shared__ float As[2][16 * 132];
    __shared__ float Bs[2][16 * 132];
    int b = blockIdx.z, t0 = blockIdx.x * 128, o0 = blockIdx.y * 128;
    int tid = threadIdx.x;
    int rt = tid >> 4, ct = tid & 15;
    int la = tid & 15, lo = tid >> 4;
    int lt = tid & 127, lr = tid >> 7;
    float coef1 = g_coef1[b];
    float cpow = g_cpow;
    const float* nb = noise + (size_t)b * DD * TKW;
    const float* xb = x + (size_t)b * TT * DD;
    unsigned long long acc2[8][4];
    ACC_ZERO();

    float ra[8], rn[8], rx[8];
    unsigned mk = 0;

#define CONV_LOAD(pc_) do {                                                   \
        _Pragma("unroll") for (int r = 0; r < 8; r++)                         \
            ra[r] = w[(size_t)(o0 + lo + 16 * r) * PCONV + (pc_) + la];       \
        mk = 0;                                                               \
        _Pragma("unroll") for (int r = 0; r < 8; r++) {                       \
            int pg = (pc_) + lr + 2 * r;                                      \
            int i = pg / 7, k = pg - 7 * i;                                   \
            int tau = t0 + lt + k;                                            \
            rn[r] = nb[(size_t)i * TKW + tau];                                \
            rx[r] = 0.f;                                                      \
            if (tau >= KW) { rx[r] = xb[(size_t)(tau - KW) * DD + i]; mk |= (1u << r); } \
        } } while (0)

#define CONV_STORE(bi) do {                                                   \
        _Pragma("unroll") for (int r = 0; r < 8; r++)                         \
            As[bi][la * 132 + lo + 16 * r] = ra[r];                           \
        _Pragma("unroll") for (int r = 0; r < 8; r++) {                       \
            float v = (coef1 * rn[r]) * cpow;                                 \
            if (mk & (1u << r)) v += rx[r];                                   \
            Bs[bi][(lr + 2 * r) * 132 + lt] = v;                              \
        } } while (0)

    CONV_LOAD(0);
    CONV_STORE(0);
    __syncthreads();
    const int NCH = PCONV / 16;   // 112
    for (int c = 0; c < NCH; c++) {
        if (c + 1 < NCH) CONV_LOAD((c + 1) * 16);
        GEMM16(As[c & 1], Bs[c & 1], rt, ct)
        if (c + 1 < NCH) CONV_STORE((c + 1) & 1);
        __syncthreads();
    }
#pragma unroll
    for (int in = 0; in < 8; in++) {
        int t = t0 + ct * 4 + (in >> 2) * 64 + (in & 3);
        float* row = dout + ((size_t)(b * TT) + t) * DD + o0;
        float4 v0 = {ACCF(0, in), ACCF(1, in), ACCF(2, in), ACCF(3, in)};
        float4 v1 = {ACCF(4, in), ACCF(5, in), ACCF(6, in), ACCF(7, in)};
        *(float4*)&row[rt * 4] = v0;
        *(float4*)&row[rt * 4 + 64] = v1;
    }
#undef CONV_LOAD
#undef CONV_STORE
}

__device__ __forceinline__ unsigned long long vq_key(float v, int m) {
    unsigned u = __float_as_uint(v);
    u = (u & 0x80000000u) ? ~u : (u | 0x80000000u);
    return ((unsigned long long)u << 32) | (unsigned)m;
}
__device__ __forceinline__ float vq_val(unsigned long long k) {
    unsigned u = (unsigned)(k >> 32);
    u = (u & 0x80000000u) ? (u & 0x7fffffffu) : ~u;
    return __uint_as_float(u);
}

// Fused merge1 + VQ, double-buffered. Distance chain: dq = fl( fl(e2+c2) - 2*dot ).
__global__ __launch_bounds__(256) void k_m1vq(const float* __restrict__ x, const float* __restrict__ emb,
                                              const float* __restrict__ w1, const float* __restrict__ a1,
                                              float* __restrict__ dout) {
    extern __shared__ float sm[];
    float* cx  = sm;                  // 256 x 132 = 33792
    float* As  = sm + 33792;          // 2 x 2112
    float* Bs  = As + 2 * 2112;       // 2 x 2112
    float* c2s = Bs + 2 * 2112;       // 128
    int b = blockIdx.y, t0 = blockIdx.x * 128;
    int tid = threadIdx.x;
    int rt = tid >> 4, ct = tid & 15;
    int la = tid & 15, lo = tid >> 4;
    float alpha = a1[0];
    const size_t rowbase = (size_t)(b * TT) + t0;
    unsigned long long acc2[8][4];

    // ---- merge1: 64 chunks (oh = c>>5, pc = (c&31)*16) ----
    {
        float ra[8]; float4 rb[2];
#define M1_LOAD(c_) do {                                                      \
        int oh_ = (c_) >> 5, pc_ = ((c_) & 31) * 16;                          \
        _Pragma("unroll") for (int r = 0; r < 8; r++)                         \
            ra[r] = w1[(size_t)(oh_ * 128 + lo + 16 * r) * (2 * DD) + pc_ + la]; \
        _Pragma("unroll") for (int h = 0; h < 2; h++) {                       \
            int id2 = tid * 2 + h;                                            \
            int t = id2 >> 2;                                                 \
            int qi = (id2 & 3) * 4;                                           \
            int i = pc_ + qi;                                                 \
            const float* src = (i < DD) ? &x[(rowbase + t) * DD + i]          \
                                        : &dout[(rowbase + t) * DD + (i - DD)]; \
            rb[h] = *(const float4*)src;                                      \
        } } while (0)
#define M1_STORE(bi) do {                                                     \
        _Pragma("unroll") for (int r = 0; r < 8; r++)                         \
            As[(bi) * 2112 + la * 132 + lo + 16 * r] = ra[r];                 \
        _Pragma("unroll") for (int h = 0; h < 2; h++) {                       \
            int id2 = tid * 2 + h;                                            \
            int t = id2 >> 2;                                                 \
            int qi = (id2 & 3) * 4;                                           \
            Bs[(bi) * 2112 + (qi + 0) * 132 + t] = rb[h].x;                   \
            Bs[(bi) * 2112 + (qi + 1) * 132 + t] = rb[h].y;                   \
            Bs[(bi) * 2112 + (qi + 2) * 132 + t] = rb[h].z;                   \
            Bs[(bi) * 2112 + (qi + 3) * 132 + t] = rb[h].w;                   \
        } } while (0)

        M1_LOAD(0);
        M1_STORE(0);
        __syncthreads();
        for (int c = 0; c < 64; c++) {
            if ((c & 31) == 0) ACC_ZERO();
            if (c + 1 < 64) M1_LOAD(c + 1);
            GEMM16((As + (c & 1) * 2112), (Bs + (c & 1) * 2112), rt, ct)
            if (c + 1 < 64) M1_STORE((c + 1) & 1);
            if ((c & 31) == 31) {
                int o0 = (c >> 5) * 128;
#pragma unroll
                for (int im = 0; im < 8; im++) {
                    int o = o0 + rt * 4 + (im >> 2) * 64 + (im & 3);
                    float4 v0 = {prelu(ACCF(im, 0), alpha), prelu(ACCF(im, 1), alpha), prelu(ACCF(im, 2), alpha), prelu(ACCF(im, 3), alpha)};
                    float4 v1 = {prelu(ACCF(im, 4), alpha), prelu(ACCF(im, 5), alpha), prelu(ACCF(im, 6), alpha), prelu(ACCF(im, 7), alpha)};
                    *(float4*)&cx[o * 132 + ct * 4] = v0;
                    *(float4*)&cx[o * 132 + ct * 4 + 64] = v1;
                }
            }
            __syncthreads();
        }
#undef M1_LOAD
#undef M1_STORE
    }

    // ---- c2[n] ----
    if (tid < 128) {
        float c2 = 0.f;
        for (int o = 0; o < DD; o++) { float v = cx[o * 132 + tid]; c2 = fmaf(v, v, c2); }
        c2s[tid] = c2;
    }
    __syncthreads();

    // ---- VQ: 128 chunks (mt = z>>4, dc = (z&15)*16) ----
    int cmt = tid & 15, cnt = tid >> 4;
    int dd_ = tid & 15, lm = tid >> 4;
    float myc2[8];
#pragma unroll
    for (int in = 0; in < 8; in++) myc2[in] = c2s[cnt * 4 + (in >> 2) * 64 + (in & 3)];
    unsigned long long b1[8], b2[8];
#pragma unroll
    for (int i = 0; i < 8; i++) { b1[i] = 0xFFFFFFFFFFFFFFFFull; b2[i] = 0xFFFFFFFFFFFFFFFFull; }
    {
        float re[8];
#define VQ_LOAD(z_) do {                                                      \
        int m0_ = ((z_) >> 4) * 128, dc_ = ((z_) & 15) * 16;                  \
        _Pragma("unroll") for (int r = 0; r < 8; r++)                         \
            re[r] = emb[(size_t)(m0_ + lm + 16 * r) * DD + dc_ + dd_];        \
        } while (0)
#define VQ_STORE(bi) do {                                                     \
        _Pragma("unroll") for (int r = 0; r < 8; r++)                         \
            Bs[(bi) * 2112 + dd_ * 132 + lm + 16 * r] = re[r];                \
        } while (0)

        VQ_LOAD(0);
        VQ_STORE(0);
        __syncthreads();
        for (int z = 0; z < 128; z++) {
            if ((z & 15) == 0) ACC_ZERO();
            if (z + 1 < 128) VQ_LOAD(z + 1);
            GEMM16((Bs + (z & 1) * 2112), (cx + (z & 15) * 16 * 132), cmt, cnt)
            if (z + 1 < 128) VQ_STORE((z + 1) & 1);
            if ((z & 15) == 15) {
                int m0 = (z >> 4) * 128;
                float e2v[8];
#pragma unroll
                for (int im = 0; im < 8; im++)
                    e2v[im] = g_e2[m0 + cmt * 4 + (im >> 2) * 64 + (im & 3)];
#pragma unroll
                for (int in = 0; in < 8; in++) {
#pragma unroll
                    for (int im = 0; im < 8; im++) {
                        int ml = cmt * 4 + (im >> 2) * 64 + (im & 3);
                        float t1 = e2v[im] + myc2[in];
                        float dq = t1 - 2.0f * ACCF(im, in);
                        unsigned long long key = vq_key(dq, m0 + ml);
                        if (key < b1[in]) { b2[in] = b1[in]; b1[in] = key; }
                        else if (key < b2[in]) b2[in] = key;
                    }
                }
            }
            __syncthreads();
        }
#undef VQ_LOAD
#undef VQ_STORE
    }

#pragma unroll
    for (int in = 0; in < 8; in++) {
        unsigned long long k1 = b1[in], k2 = b2[in];
#pragma unroll
        for (int off = 8; off; off >>= 1) {
            unsigned long long o1 = __shfl_xor_sync(0xffffffffu, k1, off);
            unsigned long long o2 = __shfl_xor_sync(0xffffffffu, k2, off);
            unsigned long long lo = (k1 < o1) ? k1 : o1;
            unsigned long long hi = (k1 < o1) ? o1 : k1;
            unsigned long long m22 = (k2 < o2) ? k2 : o2;
            k2 = (hi < m22) ? hi : m22;
            k1 = lo;
        }
        if (cmt == 0) {
            int ncol = cnt * 4 + (in >> 2) * 64 + (in & 3);
            int m1 = (int)(k1 & 0xFFFFFFFFull);
            int m2 = (int)(k2 & 0xFFFFFFFFull);
            int mwin = m1;
            float v1 = vq_val(k1), v2 = vq_val(k2);
            if (v2 - v1 < 1e-4f) {
                double d1 = 0.0, d2 = 0.0;
                const float* e1 = emb + (size_t)m1 * DD;
                const float* e2p = emb + (size_t)m2 * DD;
                for (int o = 0; o < DD; o++) {
                    double c = (double)cx[o * 132 + ncol];
                    d1 += c * (double)e1[o];
                    d2 += c * (double)e2p[o];
                }
                float c2n = myc2[in];
                float q1 = (g_e2[m1] + c2n) - 2.0f * (float)d1;
                float q2 = (g_e2[m2] + c2n) - 2.0f * (float)d2;
                if (q2 < q1 || (q2 == q1 && m2 < m1)) mwin = m2;
            }
            int n = t0 + ncol;
            dout[QELEMS + (size_t)b * TT + n] = (float)mwin;
            atomicAdd(&g_counts[mwin], 1);
        }
    }
}

__global__ void k_loss(const float* __restrict__ x, const float* __restrict__ emb,
                       const float* __restrict__ dout) {
    int n = blockIdx.x * 8 + (threadIdx.x >> 5);
    int d0 = (threadIdx.x & 31) * 8;
    int m = (int)dout[QELEMS + n];
    size_t base = (size_t)n * DD + d0;
    size_t ebase = (size_t)m * DD + d0;
    float sc = 0.f, sp = 0.f;
#pragma unroll
    for (int h = 0; h < 2; h++) {
        float4 xv = *(const float4*)&x[base + h * 4];
        float4 cv = *(const float4*)&dout[base + h * 4];
        float4 qv = *(const float4*)&emb[ebase + h * 4];
        float d1, d2;
        d1 = xv.x - cv.x - qv.x; sc += d1 * d1; d2 = cv.x - xv.x; sp += d2 * d2;
        d1 = xv.y - cv.y - qv.y; sc += d1 * d1; d2 = cv.y - xv.y; sp += d2 * d2;
        d1 = xv.z - cv.z - qv.z; sc += d1 * d1; d2 = cv.z - xv.z; sp += d2 * d2;
        d1 = xv.w - cv.w - qv.w; sc += d1 * d1; d2 = cv.w - xv.w; sp += d2 * d2;
    }
    __shared__ double red[256];
    red[threadIdx.x] = (double)sc; __syncthreads();
    for (int st = 128; st; st >>= 1) { if (threadIdx.x < st) red[threadIdx.x] += red[threadIdx.x + st]; __syncthreads(); }
    if (threadIdx.x == 0) atomicAdd(&g_commit, red[0]);
    __syncthreads();
    red[threadIdx.x] = (double)sp; __syncthreads();
    for (int st = 128; st; st >>= 1) { if (threadIdx.x < st) red[threadIdx.x] += red[threadIdx.x + st]; __syncthreads(); }
    if (threadIdx.x == 0) atomicAdd(&g_pred, red[0]);
}

__global__ __launch_bounds__(256) void k_merge2(const float* __restrict__ emb, const float* __restrict__ w2,
                                                const float* __restrict__ a2, float* __restrict__ dout) {
    extern __shared__ float sm[];
    float* ctxs = sm;                 // 256 x 132
    float* As   = sm + 33792;         // 2 x 2112
    float* Bs   = As + 2 * 2112;      // 2 x 2112
    int*   idxs = (int*)(Bs + 2 * 2112);   // 128
    int b = blockIdx.y, t0 = blockIdx.x * 128;
    int tid = threadIdx.x;
    int rt = tid >> 4, ct = tid & 15;
    int la = tid & 15, lo = tid >> 4;
    float alpha = a2[0];
    const size_t rowbase = (size_t)(b * TT) + t0;
    unsigned long long acc2[8][4];

    for (int k2 = 0; k2 < 32; k2++) {
        int id4 = k2 * 256 + tid;
        int t = id4 >> 6;
        int q = id4 & 63;
        float4 v = *(const float4*)&dout[(rowbase + t) * DD + q * 4];
        ctxs[(q * 4 + 0) * 132 + t] = v.x;
        ctxs[(q * 4 + 1) * 132 + t] = v.y;
        ctxs[(q * 4 + 2) * 132 + t] = v.z;
        ctxs[(q * 4 + 3) * 132 + t] = v.w;
    }
    if (tid < 128) idxs[tid] = (int)dout[QELEMS + (size_t)b * TT + t0 + tid];
    __syncthreads();

    {
        float ra[8]; float4 rb[2];
#define M2_LOAD(c_) do {                                                      \
        int oh_ = (c_) >> 5, pc_ = ((c_) & 31) * 16;                          \
        _Pragma("unroll") for (int r = 0; r < 8; r++)                         \
            ra[r] = w2[(size_t)(oh_ * 128 + lo + 16 * r) * (2 * DD) + pc_ + la]; \
        if (pc_ < DD) {                                                       \
            _Pragma("unroll") for (int h = 0; h < 2; h++) {                   \
                int id2 = tid * 2 + h;                                        \
                int t = id2 >> 2;                                             \
                int qi = (id2 & 3) * 4;                                       \
                rb[h] = *(const float4*)&emb[(size_t)idxs[t] * DD + pc_ + qi];\
            }                                                                 \
        } } while (0)
#define M2_STORE(c_, bi) do {                                                 \
        int pc_ = ((c_) & 31) * 16;                                           \
        _Pragma("unroll") for (int r = 0; r < 8; r++)                         \
            As[(bi) * 2112 + la * 132 + lo + 16 * r] = ra[r];                 \
        if (pc_ < DD) {                                                       \
            _Pragma("unroll") for (int h = 0; h < 2; h++) {                   \
                int id2 = tid * 2 + h;                                        \
                int t = id2 >> 2;                                             \
                int qi = (id2 & 3) * 4;                                       \
                Bs[(bi) * 2112 + (qi + 0) * 132 + t] = rb[h].x;               \
                Bs[(bi) * 2112 + (qi + 1) * 132 + t] = rb[h].y;               \
                Bs[(bi) * 2112 + (qi + 2) * 132 + t] = rb[h].z;               \
                Bs[(bi) * 2112 + (qi + 3) * 132 + t] = rb[h].w;               \
            }                                                                 \
        } } while (0)

        M2_LOAD(0);
        M2_STORE(0, 0);
        __syncthreads();
        for (int c = 0; c < 64; c++) {
            if ((c & 31) == 0) ACC_ZERO();
            if (c + 1 < 64) M2_LOAD(c + 1);
            int pc = (c & 31) * 16;
            if (pc < DD) {
                GEMM16((As + (c & 1) * 2112), (Bs + (c & 1) * 2112), rt, ct)
            } else {
                GEMM16((As + (c & 1) * 2112), (ctxs + (pc - DD) * 132), rt, ct)
            }
            if (c + 1 < 64) M2_STORE(c + 1, (c + 1) & 1);
            if ((c & 31) == 31) {
                int o0 = (c >> 5) * 128;
#pragma unroll
                for (int in = 0; in < 8; in++) {
                    int t = t0 + ct * 4 + (in >> 2) * 64 + (in & 3);
                    float* row = dout + ((size_t)(b * TT) + t) * DD + o0;
                    float4 v0 = {prelu(ACCF(0, in), alpha), prelu(ACCF(1, in), alpha), prelu(ACCF(2, in), alpha), prelu(ACCF(3, in), alpha)};
                    float4 v1 = {prelu(ACCF(4, in), alpha), prelu(ACCF(5, in), alpha), prelu(ACCF(6, in), alpha), prelu(ACCF(7, in), alpha)};
                    *(float4*)&row[rt * 4] = v0;
                    *(float4*)&row[rt * 4 + 64] = v1;
                }
            }
            __syncthreads();
        }
#undef M2_LOAD
#undef M2_STORE
    }
}

__global__ void k_stats(float* __restrict__ dout) {
    __shared__ float sUsed[1024];
    __shared__ float sEnt[1024];
    int m = threadIdx.x;
    float c = (float)g_counts[m];
    sUsed[m] = (c >= 1.0f) ? 1.0f : 0.0f;
    float p = c / (float)NQ;
    sEnt[m] = p * logf(p + 1e-10f);
    __syncthreads();
    for (int st = 512; st; st >>= 1) {
        if (m < st) { sUsed[m] += sUsed[m + st]; sEnt[m] += sEnt[m + st]; }
        __syncthreads();
    }
    if (m == 0) {
        dout[QELEMS + NQ + 0] = sUsed[0];
        dout[QELEMS + NQ + 1] = expf(-sEnt[0]);
        dout[QELEMS + NQ + 2] = (float)(g_commit / (double)QELEMS);
        dout[QELEMS + NQ + 3] = (float)(g_pred / (double)QELEMS);
    }
}

extern "C" void kernel_launch(void* const* d_in, const int* in_sizes, int n_in,
                              void* d_out, int out_size) {
    const float* x     = (const float*)d_in[0];
    const float* emb   = (const float*)d_in[1];
    const float* w_ctx = (const float*)d_in[2];
    const float* w1    = (const float*)d_in[3];
    const float* a1    = (const float*)d_in[4];
    const float* w2    = (const float*)d_in[5];
    const float* a2    = (const float*)d_in[6];
    const float* noise = (const float*)d_in[7];
    const int*   epo   = (n_in > 8) ? (const int*)d_in[8] : nullptr;
    float* dout = (float*)d_out;

    const int SMEM_DYN = (33792 + 2 * 2112 * 2 + 128) * 4;   // 169,984 B
    cudaFuncSetAttribute(k_m1vq,   cudaFuncAttributeMaxDynamicSharedMemorySize, SMEM_DYN);
    cudaFuncSetAttribute(k_merge2, cudaFuncAttributeMaxDynamicSharedMemorySize, SMEM_DYN);

    k_init<<<4, 256>>>();
    k_e2<<<MM / 256, 256>>>(emb);
    k_scale1<<<dim3(8, BB), 256>>>(x);
    k_coef<<<1, 32>>>(epo);
    k_conv<<<dim3(TT / 128, DD / 128, BB), 256>>>(w_ctx, noise, x, dout);
    k_m1vq<<<dim3(TT / 128, BB), 256, SMEM_DYN>>>(x, emb, w1, a1, dout);
    k_loss<<<NQ / 8, 256>>>(x, emb, dout);
    k_merge2<<<dim3(TT / 128, BB), 256, SMEM_DYN>>>(emb, w2, a2, dout);
    k_stats<<<1, 1024>>>(dout);
    (void)in_sizes; (void)out_size;
}

// round 13
// speedup vs baseline: 1.1742x; 1.0422x over previous
#include <cuda_runtime.h>
#include <cuda_bf16.h>
#include <math.h>
#include <stdlib.h>
#include <stdint.h>

#define BB 16
#define TT 2048
#define DD 256
#define MM 1024
#define KW 7
#define TKW (TT - 1 + KW)      /* 2054 */
#define PCONV (DD * KW)        /* 1792 */
#define NQ (BB * TT)           /* 32768 */
#define QELEMS (BB * TT * DD)  /* 8388608 */

namespace { struct HxEnv { HxEnv() { setenv("CUDA_MODULE_LOADING", "EAGER", 1); } }; static HxEnv hx_env_; }

__device__ int    g_counts[MM];
__device__ float  g_e2[MM];
__device__ double g_scalePart[BB][8];
__device__ float  g_coef1[BB];
__device__ float  g_cpow;
__device__ double g_commit;
__device__ double g_pred;

__device__ __forceinline__ float prelu(float z, float a) { return z >= 0.f ? z : a * z; }

// ---- 128x128x16 GEMM inner product, packed fma.rn.f32x2 (bit-exact per-lane RN chains).
#define GEMM16(Am, Bm, rsel, csel)                                            \
    _Pragma("unroll")                                                         \
    for (int p = 0; p < 16; p++) {                                            \
        float4 a0 = *(const float4*)&(Am)[p * 132 + (rsel) * 4];              \
        float4 a1 = *(const float4*)&(Am)[p * 132 + (rsel) * 4 + 64];         \
        ulonglong2 bq0 = *(const ulonglong2*)&(Bm)[p * 132 + (csel) * 4];     \
        ulonglong2 bq1 = *(const ulonglong2*)&(Bm)[p * 132 + (csel) * 4 + 64];\
        float av[8] = {a0.x, a0.y, a0.z, a0.w, a1.x, a1.y, a1.z, a1.w};       \
        unsigned long long bv2[4] = {bq0.x, bq0.y, bq1.x, bq1.y};             \
        _Pragma("unroll")                                                     \
        for (int i_ = 0; i_ < 8; i_++) {                                      \
            unsigned long long a2_;                                           \
            asm("mov.b64 %0, {%1, %1};" : "=l"(a2_) : "f"(av[i_]));           \
            _Pragma("unroll")                                                 \
            for (int j_ = 0; j_ < 4; j_++)                                    \
                asm("fma.rn.f32x2 %0, %1, %2, %0;"                            \
                    : "+l"(acc2[i_][j_]) : "l"(a2_), "l"(bv2[j_]));           \
        }                                                                     \
    }

#define ACCF(i_, j_) \
    __uint_as_float((unsigned)(((j_) & 1) ? (acc2[(i_)][(j_) >> 1] >> 32) : acc2[(i_)][(j_) >> 1]))

#define ACC_ZERO() do { _Pragma("unroll") for (int i_ = 0; i_ < 8; i_++) \
    _Pragma("unroll") for (int j_ = 0; j_ < 4; j_++) acc2[i_][j_] = 0ull; } while (0)

__device__ __forceinline__ void mma16816(float& c0, float& c1, float& c2, float& c3,
                                         uint32_t a0, uint32_t a1, uint32_t a2, uint32_t a3,
                                         uint32_t b0, uint32_t b1) {
    asm volatile(
        "mma.sync.aligned.m16n8k16.row.col.f32.bf16.bf16.f32 "
        "{%0,%1,%2,%3}, {%4,%5,%6,%7}, {%8,%9}, {%0,%1,%2,%3};"
        : "+f"(c0), "+f"(c1), "+f"(c2), "+f"(c3)
        : "r"(a0), "r"(a1), "r"(a2), "r"(a3), "r"(b0), "r"(b1));
}

__global__ void k_init() {
    int n = blockIdx.x * blockDim.x + threadIdx.x;
    if (n < MM) g_counts[n] = 0;
    if (n == 0) { g_commit = 0.0; g_pred = 0.0; }
}

__global__ void k_e2(const float* __restrict__ emb) {
    int m = blockIdx.x * 256 + threadIdx.x;
    const float4* r = (const float4*)(emb + (size_t)m * DD);
    double s = 0.0;
#pragma unroll 8
    for (int j = 0; j < DD / 4; j++) {
        float4 v = r[j];
        s += (double)v.x * v.x + (double)v.y * v.y + (double)v.z * v.z + (double)v.w * v.w;
    }
    g_e2[m] = (float)s;
}

__global__ void k_scale1(const float* __restrict__ x) {
    const int NE = (TT - 1) * DD;
    int b = blockIdx.y;
    int per = NE / 8;
    int start = blockIdx.x * per;
    const float* xb = x + (size_t)b * TT * DD;
    double s = 0.0;
    for (int j = start + threadIdx.x; j < start + per; j += blockDim.x) { float v = xb[j]; s += (double)v * v; }
    __shared__ double sh[256];
    sh[threadIdx.x] = s; __syncthreads();
    for (int st = 128; st; st >>= 1) { if (threadIdx.x < st) sh[threadIdx.x] += sh[threadIdx.x + st]; __syncthreads(); }
    if (threadIdx.x == 0) g_scalePart[b][blockIdx.x] = sh[0];
}

__global__ void k_coef(const int* __restrict__ epoPtr) {
    int b = threadIdx.x;
    if (b >= BB) return;
    double ef = 5.0;
    if (epoPtr) {
        int raw = epoPtr[0];
        ef = (raw >= 0 && raw <= 100000) ? (double)raw : (double)__int_as_float(raw);
    }
    double s = 0.0;
    for (int j = 0; j < 8; j++) s += g_scalePart[b][j];
    double mean = s / (double)(DD * TKW);
    g_coef1[b] = (float)(0.5 * sqrt(mean));
    if (b == 0) g_cpow = (float)pow(0.5, ef * 0.1);
}

// ctx conv as GEMM, double-buffered smem pipeline (unchanged from R11).
__global__ __launch_bounds__(256) void k_conv(const float* __restrict__ w, const float* __restrict__ noise,
                                              const float* __restrict__ x, float* __restrict__ dout) {
    __shared__ float As[2][16 * 132];
    __shared__ float Bs[2][16 * 132];
    int b = blockIdx.z, t0 = blockIdx.x * 128, o0 = blockIdx.y * 128;
    int tid = threadIdx.x;
    int rt = tid >> 4, ct = tid & 15;
    int la = tid & 15, lo = tid >> 4;
    int lt = tid & 127, lr = tid >> 7;
    float coef1 = g_coef1[b];
    float cpow = g_cpow;
    const float* nb = noise + (size_t)b * DD * TKW;
    const float* xb = x + (size_t)b * TT * DD;
    unsigned long long acc2[8][4];
    ACC_ZERO();

    float ra[8], rn[8], rx[8];
    unsigned mk = 0;

#define CONV_LOAD(pc_) do {                                                   \
        _Pragma("unroll") for (int r = 0; r < 8; r++)                         \
            ra[r] = w[(size_t)(o0 + lo + 16 * r) * PCONV + (pc_) + la];       \
        mk = 0;                                                               \
        _Pragma("unroll") for (int r = 0; r < 8; r++) {                       \
            int pg = (pc_) + lr + 2 * r;                                      \
            int i = pg / 7, k = pg - 7 * i;                                   \
            int tau = t0 + lt + k;                                            \
            rn[r] = nb[(size_t)i * TKW + tau];                                \
            rx[r] = 0.f;                                                      \
            if (tau >= KW) { rx[r] = xb[(size_t)(tau - KW) * DD + i]; mk |= (1u << r); } \
        } } while (0)

#define CONV_STORE(bi) do {                                                   \
        _Pragma("unroll") for (int r = 0; r < 8; r++)                         \
            As[bi][la * 132 + lo + 16 * r] = ra[r];                           \
        _Pragma("unroll") for (int r = 0; r < 8; r++) {                       \
            float v = (coef1 * rn[r]) * cpow;                                 \
            if (mk & (1u << r)) v += rx[r];                                   \
            Bs[bi][(lr + 2 * r) * 132 + lt] = v;                              \
        } } while (0)

    CONV_LOAD(0);
    CONV_STORE(0);
    __syncthreads();
    const int NCH = PCONV / 16;   // 112
    for (int c = 0; c < NCH; c++) {
        if (c + 1 < NCH) CONV_LOAD((c + 1) * 16);
        GEMM16(As[c & 1], Bs[c & 1], rt, ct)
        if (c + 1 < NCH) CONV_STORE((c + 1) & 1);
        __syncthreads();
    }
#pragma unroll
    for (int in = 0; in < 8; in++) {
        int t = t0 + ct * 4 + (in >> 2) * 64 + (in & 3);
        float* row = dout + ((size_t)(b * TT) + t) * DD + o0;
        float4 v0 = {ACCF(0, in), ACCF(1, in), ACCF(2, in), ACCF(3, in)};
        float4 v1 = {ACCF(4, in), ACCF(5, in), ACCF(6, in), ACCF(7, in)};
        *(float4*)&row[rt * 4] = v0;
        *(float4*)&row[rt * 4 + 64] = v1;
    }
#undef CONV_LOAD
#undef CONV_STORE
}

__device__ __forceinline__ unsigned long long vq_key(float v, int m) {
    unsigned u = __float_as_uint(v);
    u = (u & 0x80000000u) ? ~u : (u | 0x80000000u);
    return ((unsigned long long)u << 32) | (unsigned)m;
}
__device__ __forceinline__ float vq_val(unsigned long long k) {
    unsigned u = (unsigned)(k >> 32);
    u = (u & 0x80000000u) ? (u & 0x7fffffffu) : ~u;
    return __uint_as_float(u);
}

// Fused merge1 + VQ (unchanged from R11 — the fragile rounding-chain part).
__global__ __launch_bounds__(256) void k_m1vq(const float* __restrict__ x, const float* __restrict__ emb,
                                              const float* __restrict__ w1, const float* __restrict__ a1,
                                              float* __restrict__ dout) {
    extern __shared__ float sm[];
    float* cx  = sm;                  // 256 x 132 = 33792
    float* As  = sm + 33792;          // 2 x 2112
    float* Bs  = As + 2 * 2112;       // 2 x 2112
    float* c2s = Bs + 2 * 2112;       // 128
    int b = blockIdx.y, t0 = blockIdx.x * 128;
    int tid = threadIdx.x;
    int rt = tid >> 4, ct = tid & 15;
    int la = tid & 15, lo = tid >> 4;
    float alpha = a1[0];
    const size_t rowbase = (size_t)(b * TT) + t0;
    unsigned long long acc2[8][4];

    {
        float ra[8]; float4 rb[2];
#define M1_LOAD(c_) do {                                                      \
        int oh_ = (c_) >> 5, pc_ = ((c_) & 31) * 16;                          \
        _Pragma("unroll") for (int r = 0; r < 8; r++)                         \
            ra[r] = w1[(size_t)(oh_ * 128 + lo + 16 * r) * (2 * DD) + pc_ + la]; \
        _Pragma("unroll") for (int h = 0; h < 2; h++) {                       \
            int id2 = tid * 2 + h;                                            \
            int t = id2 >> 2;                                                 \
            int qi = (id2 & 3) * 4;                                           \
            int i = pc_ + qi;                                                 \
            const float* src = (i < DD) ? &x[(rowbase + t) * DD + i]          \
                                        : &dout[(rowbase + t) * DD + (i - DD)]; \
            rb[h] = *(const float4*)src;                                      \
        } } while (0)
#define M1_STORE(bi) do {                                                     \
        _Pragma("unroll") for (int r = 0; r < 8; r++)                         \
            As[(bi) * 2112 + la * 132 + lo + 16 * r] = ra[r];                 \
        _Pragma("unroll") for (int h = 0; h < 2; h++) {                       \
            int id2 = tid * 2 + h;                                            \
            int t = id2 >> 2;                                                 \
            int qi = (id2 & 3) * 4;                                           \
            Bs[(bi) * 2112 + (qi + 0) * 132 + t] = rb[h].x;                   \
            Bs[(bi) * 2112 + (qi + 1) * 132 + t] = rb[h].y;                   \
            Bs[(bi) * 2112 + (qi + 2) * 132 + t] = rb[h].z;                   \
            Bs[(bi) * 2112 + (qi + 3) * 132 + t] = rb[h].w;                   \
        } } while (0)

        M1_LOAD(0);
        M1_STORE(0);
        __syncthreads();
        for (int c = 0; c < 64; c++) {
            if ((c & 31) == 0) ACC_ZERO();
            if (c + 1 < 64) M1_LOAD(c + 1);
            GEMM16((As + (c & 1) * 2112), (Bs + (c & 1) * 2112), rt, ct)
            if (c + 1 < 64) M1_STORE((c + 1) & 1);
            if ((c & 31) == 31) {
                int o0 = (c >> 5) * 128;
#pragma unroll
                for (int im = 0; im < 8; im++) {
                    int o = o0 + rt * 4 + (im >> 2) * 64 + (im & 3);
                    float4 v0 = {prelu(ACCF(im, 0), alpha), prelu(ACCF(im, 1), alpha), prelu(ACCF(im, 2), alpha), prelu(ACCF(im, 3), alpha)};
                    float4 v1 = {prelu(ACCF(im, 4), alpha), prelu(ACCF(im, 5), alpha), prelu(ACCF(im, 6), alpha), prelu(ACCF(im, 7), alpha)};
                    *(float4*)&cx[o * 132 + ct * 4] = v0;
                    *(float4*)&cx[o * 132 + ct * 4 + 64] = v1;
                }
            }
            __syncthreads();
        }
#undef M1_LOAD
#undef M1_STORE
    }

    if (tid < 128) {
        float c2 = 0.f;
        for (int o = 0; o < DD; o++) { float v = cx[o * 132 + tid]; c2 = fmaf(v, v, c2); }
        c2s[tid] = c2;
    }
    __syncthreads();

    int cmt = tid & 15, cnt = tid >> 4;
    int dd_ = tid & 15, lm = tid >> 4;
    float myc2[8];
#pragma unroll
    for (int in = 0; in < 8; in++) myc2[in] = c2s[cnt * 4 + (in >> 2) * 64 + (in & 3)];
    unsigned long long b1[8], b2[8];
#pragma unroll
    for (int i = 0; i < 8; i++) { b1[i] = 0xFFFFFFFFFFFFFFFFull; b2[i] = 0xFFFFFFFFFFFFFFFFull; }
    {
        float re[8];
#define VQ_LOAD(z_) do {                                                      \
        int m0_ = ((z_) >> 4) * 128, dc_ = ((z_) & 15) * 16;                  \
        _Pragma("unroll") for (int r = 0; r < 8; r++)                         \
            re[r] = emb[(size_t)(m0_ + lm + 16 * r) * DD + dc_ + dd_];        \
        } while (0)
#define VQ_STORE(bi) do {                                                     \
        _Pragma("unroll") for (int r = 0; r < 8; r++)                         \
            Bs[(bi) * 2112 + dd_ * 132 + lm + 16 * r] = re[r];                \
        } while (0)

        VQ_LOAD(0);
        VQ_STORE(0);
        __syncthreads();
        for (int z = 0; z < 128; z++) {
            if ((z & 15) == 0) ACC_ZERO();
            if (z + 1 < 128) VQ_LOAD(z + 1);
            GEMM16((Bs + (z & 1) * 2112), (cx + (z & 15) * 16 * 132), cmt, cnt)
            if (z + 1 < 128) VQ_STORE((z + 1) & 1);
            if ((z & 15) == 15) {
                int m0 = (z >> 4) * 128;
                float e2v[8];
#pragma unroll
                for (int im = 0; im < 8; im++)
                    e2v[im] = g_e2[m0 + cmt * 4 + (im >> 2) * 64 + (im & 3)];
#pragma unroll
                for (int in = 0; in < 8; in++) {
#pragma unroll
                    for (int im = 0; im < 8; im++) {
                        int ml = cmt * 4 + (im >> 2) * 64 + (im & 3);
                        float t1 = e2v[im] + myc2[in];
                        float dq = t1 - 2.0f * ACCF(im, in);
                        unsigned long long key = vq_key(dq, m0 + ml);
                        if (key < b1[in]) { b2[in] = b1[in]; b1[in] = key; }
                        else if (key < b2[in]) b2[in] = key;
                    }
                }
            }
            __syncthreads();
        }
#undef VQ_LOAD
#undef VQ_STORE
    }

#pragma unroll
    for (int in = 0; in < 8; in++) {
        unsigned long long k1 = b1[in], k2 = b2[in];
#pragma unroll
        for (int off = 8; off; off >>= 1) {
            unsigned long long o1 = __shfl_xor_sync(0xffffffffu, k1, off);
            unsigned long long o2 = __shfl_xor_sync(0xffffffffu, k2, off);
            unsigned long long lo = (k1 < o1) ? k1 : o1;
            unsigned long long hi = (k1 < o1) ? o1 : k1;
            unsigned long long m22 = (k2 < o2) ? k2 : o2;
            k2 = (hi < m22) ? hi : m22;
            k1 = lo;
        }
        if (cmt == 0) {
            int ncol = cnt * 4 + (in >> 2) * 64 + (in & 3);
            int m1 = (int)(k1 & 0xFFFFFFFFull);
            int m2 = (int)(k2 & 0xFFFFFFFFull);
            int mwin = m1;
            float v1 = vq_val(k1), v2 = vq_val(k2);
            if (v2 - v1 < 1e-4f) {
                double d1 = 0.0, d2 = 0.0;
                const float* e1 = emb + (size_t)m1 * DD;
                const float* e2p = emb + (size_t)m2 * DD;
                for (int o = 0; o < DD; o++) {
                    double c = (double)cx[o * 132 + ncol];
                    d1 += c * (double)e1[o];
                    d2 += c * (double)e2p[o];
                }
                float c2n = myc2[in];
                float q1 = (g_e2[m1] + c2n) - 2.0f * (float)d1;
                float q2 = (g_e2[m2] + c2n) - 2.0f * (float)d2;
                if (q2 < q1 || (q2 == q1 && m2 < m1)) mwin = m2;
            }
            int n = t0 + ncol;
            dout[QELEMS + (size_t)b * TT + n] = (float)mwin;
            atomicAdd(&g_counts[mwin], 1);
        }
    }
}

__global__ void k_loss(const float* __restrict__ x, const float* __restrict__ emb,
                       const float* __restrict__ dout) {
    int n = blockIdx.x * 8 + (threadIdx.x >> 5);
    int d0 = (threadIdx.x & 31) * 8;
    int m = (int)dout[QELEMS + n];
    size_t base = (size_t)n * DD + d0;
    size_t ebase = (size_t)m * DD + d0;
    float sc = 0.f, sp = 0.f;
#pragma unroll
    for (int h = 0; h < 2; h++) {
        float4 xv = *(const float4*)&x[base + h * 4];
        float4 cv = *(const float4*)&dout[base + h * 4];
        float4 qv = *(const float4*)&emb[ebase + h * 4];
        float d1, d2;
        d1 = xv.x - cv.x - qv.x; sc += d1 * d1; d2 = cv.x - xv.x; sp += d2 * d2;
        d1 = xv.y - cv.y - qv.y; sc += d1 * d1; d2 = cv.y - xv.y; sp += d2 * d2;
        d1 = xv.z - cv.z - qv.z; sc += d1 * d1; d2 = cv.z - xv.z; sp += d2 * d2;
        d1 = xv.w - cv.w - qv.w; sc += d1 * d1; d2 = cv.w - xv.w; sp += d2 * d2;
    }
    __shared__ double red[256];
    red[threadIdx.x] = (double)sc; __syncthreads();
    for (int st = 128; st; st >>= 1) { if (threadIdx.x < st) red[threadIdx.x] += red[threadIdx.x + st]; __syncthreads(); }
    if (threadIdx.x == 0) atomicAdd(&g_commit, red[0]);
    __syncthreads();
    red[threadIdx.x] = (double)sp; __syncthreads();
    for (int st = 128; st; st >>= 1) { if (threadIdx.x < st) red[threadIdx.x] += red[threadIdx.x + st]; __syncthreads(); }
    if (threadIdx.x == 0) atomicAdd(&g_pred, red[0]);
}

// ---------------- merge2 via mma.sync bf16 (bf16x3 split) ----------------
// out[t][o] = PReLU( sum_i w2[o][i]*in[t][i] ), in[t] = [emb[idx[t]] ; ctx[t]]
// Per block: t=128 x o=256, K=512 in 8 chunks of 64. 8 warps = 4(o) x 2(t), warp tile 64x64.
#define M2_AH 512
#define M2_AL (M2_AH + 36864)
#define M2_BH (M2_AL + 36864)
#define M2_BL (M2_BH + 18432)
#define M2_DS 512                         /* D stage reuses chunk region */
#define M2_SMEM (512 + 128 * 260 * 4)     /* 133632 */

__global__ __launch_bounds__(256, 1) void k_merge2(const float* __restrict__ emb, const float* __restrict__ w2,
                                                   const float* __restrict__ a2, float* __restrict__ dout) {
    extern __shared__ char smc[];
    int* idxs = (int*)smc;
    uint32_t* Ah = (uint32_t*)(smc + M2_AH);
    uint32_t* Al = (uint32_t*)(smc + M2_AL);
    uint32_t* Bh = (uint32_t*)(smc + M2_BH);
    uint32_t* Bl = (uint32_t*)(smc + M2_BL);
    float* Ds = (float*)(smc + M2_DS);

    int tid = threadIdx.x;
    int wid = tid >> 5, lane = tid & 31;
    int gid = lane >> 2, tig = lane & 3;
    int b = blockIdx.y, t0 = blockIdx.x * 128;
    const size_t rowbase = (size_t)(b * TT) + t0;
    float alpha = a2[0];
    int o0w = (wid & 3) * 64;      // warp o base
    int t0w = (wid >> 2) * 64;     // warp t base

    if (tid < 128) idxs[tid] = (int)dout[QELEMS + (size_t)b * TT + t0 + tid];
    __syncthreads();

    float dfr[4][8][4];
#pragma unroll
    for (int mt = 0; mt < 4; mt++)
#pragma unroll
        for (int nt = 0; nt < 8; nt++)
#pragma unroll
            for (int q = 0; q < 4; q++) dfr[mt][nt][q] = 0.f;

    for (int c = 0; c < 8; c++) {
        int i0 = c * 64;
        // ---- stage A (w2): row o = tid, 64 cols, hi/lo split; word idx = o*36 + k/2
        {
            const float4* wr = (const float4*)(w2 + (size_t)tid * (2 * DD) + i0);
            uint32_t base = (uint32_t)tid * 36;
#pragma unroll
            for (int q = 0; q < 16; q++) {
                float4 f = wr[q];
                __nv_bfloat162 h0, h1, l0, l1;
                h0.x = __float2bfloat16(f.x); h0.y = __float2bfloat16(f.y);
                h1.x = __float2bfloat16(f.z); h1.y = __float2bfloat16(f.w);
                l0.x = __float2bfloat16(f.x - __bfloat162float(h0.x));
                l0.y = __float2bfloat16(f.y - __bfloat162float(h0.y));
                l1.x = __float2bfloat16(f.z - __bfloat162float(h1.x));
                l1.y = __float2bfloat16(f.w - __bfloat162float(h1.y));
                Ah[base + q * 2]     = *(uint32_t*)&h0;
                Ah[base + q * 2 + 1] = *(uint32_t*)&h1;
                Al[base + q * 2]     = *(uint32_t*)&l0;
                Al[base + q * 2 + 1] = *(uint32_t*)&l1;
            }
        }
        // ---- stage B (in): row t = tid&127, half hi = tid>>7 covers 32 cols
        {
            int t = tid & 127, hf = tid >> 7;
            const float* src = (i0 < DD)
                ? (emb + (size_t)idxs[t] * DD + i0 + hf * 32)
                : (dout + (rowbase + t) * DD + (i0 - DD) + hf * 32);
            uint32_t base = (uint32_t)t * 36 + (uint32_t)hf * 16;
#pragma unroll
            for (int q = 0; q < 8; q++) {
                float4 f = ((const float4*)src)[q];
                __nv_bfloat162 h0, h1, l0, l1;
                h0.x = __float2bfloat16(f.x); h0.y = __float2bfloat16(f.y);
                h1.x = __float2bfloat16(f.z); h1.y = __float2bfloat16(f.w);
                l0.x = __float2bfloat16(f.x - __bfloat162float(h0.x));
                l0.y = __float2bfloat16(f.y - __bfloat162float(h0.y));
                l1.x = __float2bfloat16(f.z - __bfloat162float(h1.x));
                l1.y = __float2bfloat16(f.w - __bfloat162float(h1.y));
                Bh[base + q * 2]     = *(uint32_t*)&h0;
                Bh[base + q * 2 + 1] = *(uint32_t*)&h1;
                Bl[base + q * 2]     = *(uint32_t*)&l0;
                Bl[base + q * 2 + 1] = *(uint32_t*)&l1;
            }
        }
        __syncthreads();

        // ---- compute: 4 k16-steps
#pragma unroll
        for (int ks = 0; ks < 4; ks++) {
            int kw = ks * 8 + tig;
            uint32_t ah[4][4], al[4][4];
#pragma unroll
            for (int mt = 0; mt < 4; mt++) {
                uint32_t r0 = (uint32_t)(o0w + mt * 16 + gid) * 36 + kw;
                uint32_t r1 = r0 + 8 * 36;
                ah[mt][0] = Ah[r0]; ah[mt][1] = Ah[r1]; ah[mt][2] = Ah[r0 + 4]; ah[mt][3] = Ah[r1 + 4];
                al[mt][0] = Al[r0]; al[mt][1] = Al[r1]; al[mt][2] = Al[r0 + 4]; al[mt][3] = Al[r1 + 4];
            }
#pragma unroll
            for (int nt = 0; nt < 8; nt++) {
                uint32_t rb = (uint32_t)(t0w + nt * 8 + gid) * 36 + kw;
                uint32_t bh0 = Bh[rb], bh1 = Bh[rb + 4];
                uint32_t bl0 = Bl[rb], bl1 = Bl[rb + 4];
#pragma unroll
                for (int mt = 0; mt < 4; mt++) {
                    float* d = dfr[mt][nt];
                    mma16816(d[0], d[1], d[2], d[3], ah[mt][0], ah[mt][1], ah[mt][2], ah[mt][3], bh0, bh1);
                    mma16816(d[0], d[1], d[2], d[3], ah[mt][0], ah[mt][1], ah[mt][2], ah[mt][3], bl0, bl1);
                    mma16816(d[0], d[1], d[2], d[3], al[mt][0], al[mt][1], al[mt][2], al[mt][3], bh0, bh1);
                }
            }
        }
        __syncthreads();
    }

    // ---- stage D to smem [t][o] stride 260, then coalesced PReLU output
#pragma unroll
    for (int mt = 0; mt < 4; mt++) {
        int orow = o0w + mt * 16 + gid;
#pragma unroll
        for (int nt = 0; nt < 8; nt++) {
            int tcol = t0w + nt * 8 + tig * 2;
            float* d = dfr[mt][nt];
            Ds[tcol * 260 + orow] = d[0];
            Ds[(tcol + 1) * 260 + orow] = d[1];
            Ds[tcol * 260 + orow + 8] = d[2];
            Ds[(tcol + 1) * 260 + orow + 8] = d[3];
        }
    }
    __syncthreads();
    for (int it = 0; it < 32; it++) {
        int id4 = it * 256 + tid;
        int o4 = id4 & 63;
        int t = id4 >> 6;
        const float* s = &Ds[t * 260 + o4 * 4];
        float4 v = {prelu(s[0], alpha), prelu(s[1], alpha), prelu(s[2], alpha), prelu(s[3], alpha)};
        *(float4*)&dout[(rowbase + t) * DD + o4 * 4] = v;
    }
}

__global__ void k_stats(float* __restrict__ dout) {
    __shared__ float sUsed[1024];
    __shared__ float sEnt[1024];
    int m = threadIdx.x;
    float c = (float)g_counts[m];
    sUsed[m] = (c >= 1.0f) ? 1.0f : 0.0f;
    float p = c / (float)NQ;
    sEnt[m] = p * logf(p + 1e-10f);
    __syncthreads();
    for (int st = 512; st; st >>= 1) {
        if (m < st) { sUsed[m] += sUsed[m + st]; sEnt[m] += sEnt[m + st]; }
        __syncthreads();
    }
    if (m == 0) {
        dout[QELEMS + NQ + 0] = sUsed[0];
        dout[QELEMS + NQ + 1] = expf(-sEnt[0]);
        dout[QELEMS + NQ + 2] = (float)(g_commit / (double)QELEMS);
        dout[QELEMS + NQ + 3] = (float)(g_pred / (double)QELEMS);
    }
}

extern "C" void kernel_launch(void* const* d_in, const int* in_sizes, int n_in,
                              void* d_out, int out_size) {
    const float* x     = (const float*)d_in[0];
    const float* emb   = (const float*)d_in[1];
    const float* w_ctx = (const float*)d_in[2];
    const float* w1    = (const float*)d_in[3];
    const float* a1    = (const float*)d_in[4];
    const float* w2    = (const float*)d_in[5];
    const float* a2    = (const float*)d_in[6];
    const float* noise = (const float*)d_in[7];
    const int*   epo   = (n_in > 8) ? (const int*)d_in[8] : nullptr;
    float* dout = (float*)d_out;

    const int SMEM_DYN = (33792 + 2 * 2112 * 2 + 128) * 4;   // 169,984 B (k_m1vq)
    cudaFuncSetAttribute(k_m1vq,   cudaFuncAttributeMaxDynamicSharedMemorySize, SMEM_DYN);
    cudaFuncSetAttribute(k_merge2, cudaFuncAttributeMaxDynamicSharedMemorySize, M2_SMEM);

    k_init<<<4, 256>>>();
    k_e2<<<MM / 256, 256>>>(emb);
    k_scale1<<<dim3(8, BB), 256>>>(x);
    k_coef<<<1, 32>>>(epo);
    k_conv<<<dim3(TT / 128, DD / 128, BB), 256>>>(w_ctx, noise, x, dout);
    k_m1vq<<<dim3(TT / 128, BB), 256, SMEM_DYN>>>(x, emb, w1, a1, dout);
    k_loss<<<NQ / 8, 256>>>(x, emb, dout);
    k_merge2<<<dim3(TT / 128, BB), 256, M2_SMEM>>>(emb, w2, a2, dout);
    k_stats<<<1, 1024>>>(dout);
    (void)in_sizes; (void)out_size;
}

// round 15
// speedup vs baseline: 1.2418x; 1.0576x over previous
#include <cuda_runtime.h>
#include <cuda_bf16.h>
#include <math.h>
#include <stdlib.h>
#include <stdint.h>

#define BB 16
#define TT 2048
#define DD 256
#define MM 1024
#define KW 7
#define TKW (TT - 1 + KW)      /* 2054 */
#define PCONV (DD * KW)        /* 1792 */
#define NQ (BB * TT)           /* 32768 */
#define QELEMS (BB * TT * DD)  /* 8388608 */

namespace { struct HxEnv { HxEnv() { setenv("CUDA_MODULE_LOADING", "EAGER", 1); } }; static HxEnv hx_env_; }

__device__ int    g_counts[MM];
__device__ float  g_e2[MM];
__device__ double g_scalePart[BB][8];
__device__ float  g_coef1[BB];
__device__ float  g_cpow;
__device__ double g_commit;
__device__ double g_pred;

__device__ __forceinline__ float prelu(float z, float a) { return z >= 0.f ? z : a * z; }

// ---- 128x128x16 GEMM inner product, packed fma.rn.f32x2 (bit-exact per-lane RN chains).
#define GEMM16(Am, Bm, rsel, csel)                                            \
    _Pragma("unroll")                                                         \
    for (int p = 0; p < 16; p++) {                                            \
        float4 a0 = *(const float4*)&(Am)[p * 132 + (rsel) * 4];              \
        float4 a1 = *(const float4*)&(Am)[p * 132 + (rsel) * 4 + 64];         \
        ulonglong2 bq0 = *(const ulonglong2*)&(Bm)[p * 132 + (csel) * 4];     \
        ulonglong2 bq1 = *(const ulonglong2*)&(Bm)[p * 132 + (csel) * 4 + 64];\
        float av[8] = {a0.x, a0.y, a0.z, a0.w, a1.x, a1.y, a1.z, a1.w};       \
        unsigned long long bv2[4] = {bq0.x, bq0.y, bq1.x, bq1.y};             \
        _Pragma("unroll")                                                     \
        for (int i_ = 0; i_ < 8; i_++) {                                      \
            unsigned long long a2_;                                           \
            asm("mov.b64 %0, {%1, %1};" : "=l"(a2_) : "f"(av[i_]));           \
            _Pragma("unroll")                                                 \
            for (int j_ = 0; j_ < 4; j_++)                                    \
                asm("fma.rn.f32x2 %0, %1, %2, %0;"                            \
                    : "+l"(acc2[i_][j_]) : "l"(a2_), "l"(bv2[j_]));           \
        }                                                                     \
    }

#define ACCF(i_, j_) \
    __uint_as_float((unsigned)(((j_) & 1) ? (acc2[(i_)][(j_) >> 1] >> 32) : acc2[(i_)][(j_) >> 1]))

#define ACC_ZERO() do { _Pragma("unroll") for (int i_ = 0; i_ < 8; i_++) \
    _Pragma("unroll") for (int j_ = 0; j_ < 4; j_++) acc2[i_][j_] = 0ull; } while (0)

__device__ __forceinline__ void mma16816(float& c0, float& c1, float& c2, float& c3,
                                         uint32_t a0, uint32_t a1, uint32_t a2, uint32_t a3,
                                         uint32_t b0, uint32_t b1) {
    asm volatile(
        "mma.sync.aligned.m16n8k16.row.col.f32.bf16.bf16.f32 "
        "{%0,%1,%2,%3}, {%4,%5,%6,%7}, {%8,%9}, {%0,%1,%2,%3};"
        : "+f"(c0), "+f"(c1), "+f"(c2), "+f"(c3)
        : "r"(a0), "r"(a1), "r"(a2), "r"(a3), "r"(b0), "r"(b1));
}

__device__ __forceinline__ uint32_t bf2hi(float x, float y, float& rx, float& ry) {
    __nv_bfloat162 h;
    h.x = __float2bfloat16(x); h.y = __float2bfloat16(y);
    rx = x - __bfloat162float(h.x);
    ry = y - __bfloat162float(h.y);
    return *(uint32_t*)&h;
}
__device__ __forceinline__ uint32_t bf2of(float x, float y) {
    __nv_bfloat162 h;
    h.x = __float2bfloat16(x); h.y = __float2bfloat16(y);
    return *(uint32_t*)&h;
}

__global__ void k_init() {
    int n = blockIdx.x * blockDim.x + threadIdx.x;
    if (n < MM) g_counts[n] = 0;
    if (n == 0) { g_commit = 0.0; g_pred = 0.0; }
}

__global__ void k_e2(const float* __restrict__ emb) {
    int m = blockIdx.x * 256 + threadIdx.x;
    const float4* r = (const float4*)(emb + (size_t)m * DD);
    double s = 0.0;
#pragma unroll 8
    for (int j = 0; j < DD / 4; j++) {
        float4 v = r[j];
        s += (double)v.x * v.x + (double)v.y * v.y + (double)v.z * v.z + (double)v.w * v.w;
    }
    g_e2[m] = (float)s;
}

__global__ void k_scale1(const float* __restrict__ x) {
    const int NE = (TT - 1) * DD;
    int b = blockIdx.y;
    int per = NE / 8;
    int start = blockIdx.x * per;
    const float* xb = x + (size_t)b * TT * DD;
    double s = 0.0;
    for (int j = start + threadIdx.x; j < start + per; j += blockDim.x) { float v = xb[j]; s += (double)v * v; }
    __shared__ double sh[256];
    sh[threadIdx.x] = s; __syncthreads();
    for (int st = 128; st; st >>= 1) { if (threadIdx.x < st) sh[threadIdx.x] += sh[threadIdx.x + st]; __syncthreads(); }
    if (threadIdx.x == 0) g_scalePart[b][blockIdx.x] = sh[0];
}

__global__ void k_coef(const int* __restrict__ epoPtr) {
    int b = threadIdx.x;
    if (b >= BB) return;
    double ef = 5.0;
    if (epoPtr) {
        int raw = epoPtr[0];
        ef = (raw >= 0 && raw <= 100000) ? (double)raw : (double)__int_as_float(raw);
    }
    double s = 0.0;
    for (int j = 0; j < 8; j++) s += g_scalePart[b][j];
    double mean = s / (double)(DD * TKW);
    g_coef1[b] = (float)(0.5 * sqrt(mean));
    if (b == 0) g_cpow = (float)pow(0.5, ef * 0.1);
}

// ctx conv as GEMM, double-buffered smem pipeline (unchanged).
__global__ __launch_bounds__(256) void k_conv(const float* __restrict__ w, const float* __restrict__ noise,
                                              const float* __restrict__ x, float* __restrict__ dout) {
    __shared__ float As[2][16 * 132];
    __shared__ float Bs[2][16 * 132];
    int b = blockIdx.z, t0 = blockIdx.x * 128, o0 = blockIdx.y * 128;
    int tid = threadIdx.x;
    int rt = tid >> 4, ct = tid & 15;
    int la = tid & 15, lo = tid >> 4;
    int lt = tid & 127, lr = tid >> 7;
    float coef1 = g_coef1[b];
    float cpow = g_cpow;
    const float* nb = noise + (size_t)b * DD * TKW;
    const float* xb = x + (size_t)b * TT * DD;
    unsigned long long acc2[8][4];
    ACC_ZERO();

    float ra[8], rn[8], rx[8];
    unsigned mk = 0;

#define CONV_LOAD(pc_) do {                                                   \
        _Pragma("unroll") for (int r = 0; r < 8; r++)                         \
            ra[r] = w[(size_t)(o0 + lo + 16 * r) * PCONV + (pc_) + la];       \
        mk = 0;                                                               \
        _Pragma("unroll") for (int r = 0; r < 8; r++) {                       \
            int pg = (pc_) + lr + 2 * r;                                      \
            int i = pg / 7, k = pg - 7 * i;                                   \
            int tau = t0 + lt + k;                                            \
            rn[r] = nb[(size_t)i * TKW + tau];                                \
            rx[r] = 0.f;                                                      \
            if (tau >= KW) { rx[r] = xb[(size_t)(tau - KW) * DD + i]; mk |= (1u << r); } \
        } } while (0)

#define CONV_STORE(bi) do {                                                   \
        _Pragma("unroll") for (int r = 0; r < 8; r++)                         \
            As[bi][la * 132 + lo + 16 * r] = ra[r];                           \
        _Pragma("unroll") for (int r = 0; r < 8; r++) {                       \
            float v = (coef1 * rn[r]) * cpow;                                 \
            if (mk & (1u << r)) v += rx[r];                                   \
            Bs[bi][(lr + 2 * r) * 132 + lt] = v;                              \
        } } while (0)

    CONV_LOAD(0);
    CONV_STORE(0);
    __syncthreads();
    const int NCH = PCONV / 16;   // 112
    for (int c = 0; c < NCH; c++) {
        if (c + 1 < NCH) CONV_LOAD((c + 1) * 16);
        GEMM16(As[c & 1], Bs[c & 1], rt, ct)
        if (c + 1 < NCH) CONV_STORE((c + 1) & 1);
        __syncthreads();
    }
#pragma unroll
    for (int in = 0; in < 8; in++) {
        int t = t0 + ct * 4 + (in >> 2) * 64 + (in & 3);
        float* row = dout + ((size_t)(b * TT) + t) * DD + o0;
        float4 v0 = {ACCF(0, in), ACCF(1, in), ACCF(2, in), ACCF(3, in)};
        float4 v1 = {ACCF(4, in), ACCF(5, in), ACCF(6, in), ACCF(7, in)};
        *(float4*)&row[rt * 4] = v0;
        *(float4*)&row[rt * 4 + 64] = v1;
    }
#undef CONV_LOAD
#undef CONV_STORE
}

__device__ __forceinline__ unsigned long long vq_key(float v, int m) {
    unsigned u = __float_as_uint(v);
    u = (u & 0x80000000u) ? ~u : (u | 0x80000000u);
    return ((unsigned long long)u << 32) | (unsigned)m;
}
__device__ __forceinline__ float vq_val(unsigned long long k) {
    unsigned u = (unsigned)(k >> 32);
    u = (u & 0x80000000u) ? (u & 0x7fffffffu) : ~u;
    return __uint_as_float(u);
}

// Fused merge1 (fp32 FFMA2, bit-exact) + VQ pass-1 via HMMA bf16x3 + exact refine.
// cx stored [t][260] (t-major): B operand for HMMA, contiguous for c2/refine.
__global__ __launch_bounds__(256, 1) void k_m1vq(const float* __restrict__ x, const float* __restrict__ emb,
                                                 const float* __restrict__ w1, const float* __restrict__ a1,
                                                 float* __restrict__ dout) {
    extern __shared__ float sm[];
    float* cx  = sm;                   // 128 x 260 = 33280 floats
    float* S   = sm + 33280;           // shared region: merge1 As/Bs (8448) or VQ emb stage (9216)
    float* c2s = sm + 42496;           // 128
    unsigned long long* red = (unsigned long long*)(sm + 42624);  // 2 x 128 x 2 ull
    float* As = S;
    float* Bs = S + 4224;
    int b = blockIdx.y, t0 = blockIdx.x * 128;
    int tid = threadIdx.x;
    int rt = tid >> 4, ct = tid & 15;
    int la = tid & 15, lo = tid >> 4;
    float alpha = a1[0];
    const size_t rowbase = (size_t)(b * TT) + t0;
    unsigned long long acc2[8][4];

    // ---- merge1: cur_x = PReLU(W1 * [x; ctx]) -- fp32 chain unchanged, epilogue transposed ----
    {
        float ra[8]; float4 rb[2];
#define M1_LOAD(c_) do {                                                      \
        int oh_ = (c_) >> 5, pc_ = ((c_) & 31) * 16;                          \
        _Pragma("unroll") for (int r = 0; r < 8; r++)                         \
            ra[r] = w1[(size_t)(oh_ * 128 + lo + 16 * r) * (2 * DD) + pc_ + la]; \
        _Pragma("unroll") for (int h = 0; h < 2; h++) {                       \
            int id2 = tid * 2 + h;                                            \
            int t = id2 >> 2;                                                 \
            int qi = (id2 & 3) * 4;                                           \
            int i = pc_ + qi;                                                 \
            const float* src = (i < DD) ? &x[(rowbase + t) * DD + i]          \
                                        : &dout[(rowbase + t) * DD + (i - DD)]; \
            rb[h] = *(const float4*)src;                                      \
        } } while (0)
#define M1_STORE(bi) do {                                                     \
        _Pragma("unroll") for (int r = 0; r < 8; r++)                         \
            As[(bi) * 2112 + la * 132 + lo + 16 * r] = ra[r];                 \
        _Pragma("unroll") for (int h = 0; h < 2; h++) {                       \
            int id2 = tid * 2 + h;                                            \
            int t = id2 >> 2;                                                 \
            int qi = (id2 & 3) * 4;                                           \
            Bs[(bi) * 2112 + (qi + 0) * 132 + t] = rb[h].x;                   \
            Bs[(bi) * 2112 + (qi + 1) * 132 + t] = rb[h].y;                   \
            Bs[(bi) * 2112 + (qi + 2) * 132 + t] = rb[h].z;                   \
            Bs[(bi) * 2112 + (qi + 3) * 132 + t] = rb[h].w;                   \
        } } while (0)

        M1_LOAD(0);
        M1_STORE(0);
        __syncthreads();
        for (int c = 0; c < 64; c++) {
            if ((c & 31) == 0) ACC_ZERO();
            if (c + 1 < 64) M1_LOAD(c + 1);
            GEMM16((As + (c & 1) * 2112), (Bs + (c & 1) * 2112), rt, ct)
            if (c + 1 < 64) M1_STORE((c + 1) & 1);
            if ((c & 31) == 31) {
                int o0 = (c >> 5) * 128;
#pragma unroll
                for (int im = 0; im < 8; im++) {
                    int o = o0 + rt * 4 + (im >> 2) * 64 + (im & 3);
#pragma unroll
                    for (int in = 0; in < 8; in++) {
                        int t = ct * 4 + (in >> 2) * 64 + (in & 3);
                        cx[t * 260 + o] = prelu(ACCF(im, in), alpha);
                    }
                }
            }
            __syncthreads();
        }
#undef M1_LOAD
#undef M1_STORE
    }

    // ---- c2[t]: same sequential fmaf order as before ----
    if (tid < 128) {
        float c2 = 0.f;
        const float* row = &cx[tid * 260];
        for (int o = 0; o < DD; o++) { float v = row[o]; c2 = fmaf(v, v, c2); }
        c2s[tid] = c2;
    }
    __syncthreads();

    // ---- VQ pass 1: HMMA bf16x3, top-2 per position ----
    int wid = tid >> 5, lane = tid & 31;
    int gid = lane >> 2, tig = lane & 3;
    int m_w = wid & 1, t_w = wid >> 1;
    uint32_t* Sh = (uint32_t*)S;       // 128 x 36 words
    uint32_t* Sl = Sh + 4608;
    unsigned long long tb1[4][2], tb2[4][2];
    float c2v[4][2];
#pragma unroll
    for (int nt = 0; nt < 4; nt++)
#pragma unroll
        for (int par = 0; par < 2; par++) {
            tb1[nt][par] = 0xFFFFFFFFFFFFFFFFull;
            tb2[nt][par] = 0xFFFFFFFFFFFFFFFFull;
            c2v[nt][par] = c2s[t_w * 32 + nt * 8 + tig * 2 + par];
        }

    for (int mt8 = 0; mt8 < 8; mt8++) {
        int m0 = mt8 * 128;
        float dfr[4][4][4];
#pragma unroll
        for (int mt = 0; mt < 4; mt++)
#pragma unroll
            for (int nt = 0; nt < 4; nt++)
#pragma unroll
                for (int q = 0; q < 4; q++) dfr[mt][nt][q] = 0.f;

        for (int ch = 0; ch < 4; ch++) {
            int d0 = ch * 64;
            // stage emb[m0 + r][d0..d0+63] -> hi/lo bf16, 36-word rows
            {
                int r = tid >> 1, hf = tid & 1;
                const float4* er = (const float4*)(emb + (size_t)(m0 + r) * DD + d0 + hf * 32);
                uint32_t base = (uint32_t)r * 36 + (uint32_t)hf * 16;
#pragma unroll
                for (int q = 0; q < 8; q++) {
                    float4 f = er[q];
                    float lx, ly, lz, lw;
                    uint32_t h0 = bf2hi(f.x, f.y, lx, ly);
                    uint32_t h1 = bf2hi(f.z, f.w, lz, lw);
                    Sh[base + q * 2] = h0;
                    Sh[base + q * 2 + 1] = h1;
                    Sl[base + q * 2] = bf2of(lx, ly);
                    Sl[base + q * 2 + 1] = bf2of(lz, lw);
                }
            }
            __syncthreads();

#pragma unroll
            for (int ks = 0; ks < 4; ks++) {
                int kw = ks * 8 + tig;
                uint32_t ah[4][4], al[4][4];
#pragma unroll
                for (int mt = 0; mt < 4; mt++) {
                    uint32_t r0 = (uint32_t)(m_w * 64 + mt * 16 + gid) * 36 + kw;
                    uint32_t r1 = r0 + 8 * 36;
                    ah[mt][0] = Sh[r0]; ah[mt][1] = Sh[r1]; ah[mt][2] = Sh[r0 + 4]; ah[mt][3] = Sh[r1 + 4];
                    al[mt][0] = Sl[r0]; al[mt][1] = Sl[r1]; al[mt][2] = Sl[r0 + 4]; al[mt][3] = Sl[r1 + 4];
                }
#pragma unroll
                for (int nt = 0; nt < 4; nt++) {
                    int t = t_w * 32 + nt * 8 + gid;
                    const float* bp = &cx[t * 260 + d0 + kw * 2];
                    float2 f0 = *(const float2*)bp;
                    float2 f1 = *(const float2*)(bp + 8);
                    float lx, ly, lz, lw;
                    uint32_t bh0 = bf2hi(f0.x, f0.y, lx, ly);
                    uint32_t bh1 = bf2hi(f1.x, f1.y, lz, lw);
                    uint32_t bl0 = bf2of(lx, ly);
                    uint32_t bl1 = bf2of(lz, lw);
#pragma unroll
                    for (int mt = 0; mt < 4; mt++) {
                        float* d = dfr[mt][nt];
                        mma16816(d[0], d[1], d[2], d[3], ah[mt][0], ah[mt][1], ah[mt][2], ah[mt][3], bh0, bh1);
                        mma16816(d[0], d[1], d[2], d[3], ah[mt][0], ah[mt][1], ah[mt][2], ah[mt][3], bl0, bl1);
                        mma16816(d[0], d[1], d[2], d[3], al[mt][0], al[mt][1], al[mt][2], al[mt][3], bh0, bh1);
                    }
                }
            }
            __syncthreads();
        }

        // fold m-tile results into top-2
#pragma unroll
        for (int mt = 0; mt < 4; mt++) {
            int mb = m0 + m_w * 64 + mt * 16 + gid;
            float e2a = g_e2[mb], e2b = g_e2[mb + 8];
#pragma unroll
            for (int nt = 0; nt < 4; nt++) {
#pragma unroll
                for (int q = 0; q < 4; q++) {
                    int m = (q & 2) ? (mb + 8) : mb;
                    float e2m = (q & 2) ? e2b : e2a;
                    int par = q & 1;
                    float dq = (e2m + c2v[nt][par]) - 2.0f * dfr[mt][nt][q];
                    unsigned long long key = vq_key(dq, m);
                    if (key < tb1[nt][par]) { tb2[nt][par] = tb1[nt][par]; tb1[nt][par] = key; }
                    else if (key < tb2[nt][par]) tb2[nt][par] = key;
                }
            }
        }
    }

    // ---- reduce over gid (lanes xor 4/8/16), publish per m-warp, final merge + refine ----
#pragma unroll
    for (int nt = 0; nt < 4; nt++) {
#pragma unroll
        for (int par = 0; par < 2; par++) {
            unsigned long long k1 = tb1[nt][par], k2 = tb2[nt][par];
#pragma unroll
            for (int off = 4; off <= 16; off <<= 1) {
                unsigned long long o1 = __shfl_xor_sync(0xffffffffu, k1, off);
                unsigned long long o2 = __shfl_xor_sync(0xffffffffu, k2, off);
                unsigned long long lo = (k1 < o1) ? k1 : o1;
                unsigned long long hi = (k1 < o1) ? o1 : k1;
                unsigned long long m22 = (k2 < o2) ? k2 : o2;
                k2 = (hi < m22) ? hi : m22;
                k1 = lo;
            }
            if (gid == 0) {
                int t = t_w * 32 + nt * 8 + tig * 2 + par;
                red[(m_w * 128 + t) * 2] = k1;
                red[(m_w * 128 + t) * 2 + 1] = k2;
            }
        }
    }
    __syncthreads();

    if (tid < 128) {
        int t = tid;
        unsigned long long a1k = red[t * 2], a2k = red[t * 2 + 1];
        unsigned long long bb1 = red[(128 + t) * 2], bb2 = red[(128 + t) * 2 + 1];
        unsigned long long k1, k2;
        if (a1k < bb1) { k1 = a1k; k2 = (a2k < bb1) ? a2k : bb1; }
        else           { k1 = bb1; k2 = (bb2 < a1k) ? bb2 : a1k; }
        int m1 = (int)(k1 & 0xFFFFFFFFull);
        int m2 = (int)(k2 & 0xFFFFFFFFull);
        int mwin = m1;
        float v1 = vq_val(k1), v2 = vq_val(k2);
        if (v2 - v1 < 1e-4f) {
            double d1 = 0.0, d2 = 0.0;
            const float* e1 = emb + (size_t)m1 * DD;
            const float* e2p = emb + (size_t)m2 * DD;
            const float* row = &cx[t * 260];
            for (int o = 0; o < DD; o++) {
                double c = (double)row[o];
                d1 += c * (double)e1[o];
                d2 += c * (double)e2p[o];
            }
            float c2n = c2s[t];
            float q1 = (g_e2[m1] + c2n) - 2.0f * (float)d1;
            float q2 = (g_e2[m2] + c2n) - 2.0f * (float)d2;
            if (q2 < q1 || (q2 == q1 && m2 < m1)) mwin = m2;
        }
        int n = t0 + t;
        dout[QELEMS + (size_t)b * TT + n] = (float)mwin;
        atomicAdd(&g_counts[mwin], 1);
    }
}

__global__ void k_loss(const float* __restrict__ x, const float* __restrict__ emb,
                       const float* __restrict__ dout) {
    int n = blockIdx.x * 8 + (threadIdx.x >> 5);
    int d0 = (threadIdx.x & 31) * 8;
    int m = (int)dout[QELEMS + n];
    size_t base = (size_t)n * DD + d0;
    size_t ebase = (size_t)m * DD + d0;
    float sc = 0.f, sp = 0.f;
#pragma unroll
    for (int h = 0; h < 2; h++) {
        float4 xv = *(const float4*)&x[base + h * 4];
        float4 cv = *(const float4*)&dout[base + h * 4];
        float4 qv = *(const float4*)&emb[ebase + h * 4];
        float d1, d2;
        d1 = xv.x - cv.x - qv.x; sc += d1 * d1; d2 = cv.x - xv.x; sp += d2 * d2;
        d1 = xv.y - cv.y - qv.y; sc += d1 * d1; d2 = cv.y - xv.y; sp += d2 * d2;
        d1 = xv.z - cv.z - qv.z; sc += d1 * d1; d2 = cv.z - xv.z; sp += d2 * d2;
        d1 = xv.w - cv.w - qv.w; sc += d1 * d1; d2 = cv.w - xv.w; sp += d2 * d2;
    }
    __shared__ double red[256];
    red[threadIdx.x] = (double)sc; __syncthreads();
    for (int st = 128; st; st >>= 1) { if (threadIdx.x < st) red[threadIdx.x] += red[threadIdx.x + st]; __syncthreads(); }
    if (threadIdx.x == 0) atomicAdd(&g_commit, red[0]);
    __syncthreads();
    red[threadIdx.x] = (double)sp; __syncthreads();
    for (int st = 128; st; st >>= 1) { if (threadIdx.x < st) red[threadIdx.x] += red[threadIdx.x + st]; __syncthreads(); }
    if (threadIdx.x == 0) atomicAdd(&g_pred, red[0]);
}

// ---------------- merge2 via mma.sync bf16 (bf16x3 split) -- unchanged from R13 ----------------
#define M2_AH 512
#define M2_AL (M2_AH + 36864)
#define M2_BH (M2_AL + 36864)
#define M2_BL (M2_BH + 18432)
#define M2_DS 512
#define M2_SMEM (512 + 128 * 260 * 4)     /* 133632 */

__global__ __launch_bounds__(256, 1) void k_merge2(const float* __restrict__ emb, const float* __restrict__ w2,
                                                   const float* __restrict__ a2, float* __restrict__ dout) {
    extern __shared__ char smc[];
    int* idxs = (int*)smc;
    uint32_t* Ah = (uint32_t*)(smc + M2_AH);
    uint32_t* Al = (uint32_t*)(smc + M2_AL);
    uint32_t* Bh = (uint32_t*)(smc + M2_BH);
    uint32_t* Bl = (uint32_t*)(smc + M2_BL);
    float* Ds = (float*)(smc + M2_DS);

    int tid = threadIdx.x;
    int wid = tid >> 5, lane = tid & 31;
    int gid = lane >> 2, tig = lane & 3;
    int b = blockIdx.y, t0 = blockIdx.x * 128;
    const size_t rowbase = (size_t)(b * TT) + t0;
    float alpha = a2[0];
    int o0w = (wid & 3) * 64;
    int t0w = (wid >> 2) * 64;

    if (tid < 128) idxs[tid] = (int)dout[QELEMS + (size_t)b * TT + t0 + tid];
    __syncthreads();

    float dfr[4][8][4];
#pragma unroll
    for (int mt = 0; mt < 4; mt++)
#pragma unroll
        for (int nt = 0; nt < 8; nt++)
#pragma unroll
            for (int q = 0; q < 4; q++) dfr[mt][nt][q] = 0.f;

    for (int c = 0; c < 8; c++) {
        int i0 = c * 64;
        {
            const float4* wr = (const float4*)(w2 + (size_t)tid * (2 * DD) + i0);
            uint32_t base = (uint32_t)tid * 36;
#pragma unroll
            for (int q = 0; q < 16; q++) {
                float4 f = wr[q];
                float lx, ly, lz, lw;
                uint32_t h0 = bf2hi(f.x, f.y, lx, ly);
                uint32_t h1 = bf2hi(f.z, f.w, lz, lw);
                Ah[base + q * 2] = h0;
                Ah[base + q * 2 + 1] = h1;
                Al[base + q * 2] = bf2of(lx, ly);
                Al[base + q * 2 + 1] = bf2of(lz, lw);
            }
        }
        {
            int t = tid & 127, hf = tid >> 7;
            const float* src = (i0 < DD)
                ? (emb + (size_t)idxs[t] * DD + i0 + hf * 32)
                : (dout + (rowbase + t) * DD + (i0 - DD) + hf * 32);
            uint32_t base = (uint32_t)t * 36 + (uint32_t)hf * 16;
#pragma unroll
            for (int q = 0; q < 8; q++) {
                float4 f = ((const float4*)src)[q];
                float lx, ly, lz, lw;
                uint32_t h0 = bf2hi(f.x, f.y, lx, ly);
                uint32_t h1 = bf2hi(f.z, f.w, lz, lw);
                Bh[base + q * 2] = h0;
                Bh[base + q * 2 + 1] = h1;
                Bl[base + q * 2] = bf2of(lx, ly);
                Bl[base + q * 2 + 1] = bf2of(lz, lw);
            }
        }
        __syncthreads();

#pragma unroll
        for (int ks = 0; ks < 4; ks++) {
            int kw = ks * 8 + tig;
            uint32_t ah[4][4], al[4][4];
#pragma unroll
            for (int mt = 0; mt < 4; mt++) {
                uint32_t r0 = (uint32_t)(o0w + mt * 16 + gid) * 36 + kw;
                uint32_t r1 = r0 + 8 * 36;
                ah[mt][0] = Ah[r0]; ah[mt][1] = Ah[r1]; ah[mt][2] = Ah[r0 + 4]; ah[mt][3] = Ah[r1 + 4];
                al[mt][0] = Al[r0]; al[mt][1] = Al[r1]; al[mt][2] = Al[r0 + 4]; al[mt][3] = Al[r1 + 4];
            }
#pragma unroll
            for (int nt = 0; nt < 8; nt++) {
                uint32_t rb = (uint32_t)(t0w + nt * 8 + gid) * 36 + kw;
                uint32_t bh0 = Bh[rb], bh1 = Bh[rb + 4];
                uint32_t bl0 = Bl[rb], bl1 = Bl[rb + 4];
#pragma unroll
                for (int mt = 0; mt < 4; mt++) {
                    float* d = dfr[mt][nt];
                    mma16816(d[0], d[1], d[2], d[3], ah[mt][0], ah[mt][1], ah[mt][2], ah[mt][3], bh0, bh1);
                    mma16816(d[0], d[1], d[2], d[3], ah[mt][0], ah[mt][1], ah[mt][2], ah[mt][3], bl0, bl1);
                    mma16816(d[0], d[1], d[2], d[3], al[mt][0], al[mt][1], al[mt][2], al[mt][3], bh0, bh1);
                }
            }
        }
        __syncthreads();
    }

#pragma unroll
    for (int mt = 0; mt < 4; mt++) {
        int orow = o0w + mt * 16 + gid;
#pragma unroll
        for (int nt = 0; nt < 8; nt++) {
            int tcol = t0w + nt * 8 + tig * 2;
            float* d = dfr[mt][nt];
            Ds[tcol * 260 + orow] = d[0];
            Ds[(tcol + 1) * 260 + orow] = d[1];
            Ds[tcol * 260 + orow + 8] = d[2];
            Ds[(tcol + 1) * 260 + orow + 8] = d[3];
        }
    }
    __syncthreads();
    for (int it = 0; it < 32; it++) {
        int id4 = it * 256 + tid;
        int o4 = id4 & 63;
        int t = id4 >> 6;
        const float* s = &Ds[t * 260 + o4 * 4];
        float4 v = {prelu(s[0], alpha), prelu(s[1], alpha), prelu(s[2], alpha), prelu(s[3], alpha)};
        *(float4*)&dout[(rowbase + t) * DD + o4 * 4] = v;
    }
}

__global__ void k_stats(float* __restrict__ dout) {
    __shared__ float sUsed[1024];
    __shared__ float sEnt[1024];
    int m = threadIdx.x;
    float c = (float)g_counts[m];
    sUsed[m] = (c >= 1.0f) ? 1.0f : 0.0f;
    float p = c / (float)NQ;
    sEnt[m] = p * logf(p + 1e-10f);
    __syncthreads();
    for (int st = 512; st; st >>= 1) {
        if (m < st) { sUsed[m] += sUsed[m + st]; sEnt[m] += sEnt[m + st]; }
        __syncthreads();
    }
    if (m == 0) {
        dout[QELEMS + NQ + 0] = sUsed[0];
        dout[QELEMS + NQ + 1] = expf(-sEnt[0]);
        dout[QELEMS + NQ + 2] = (float)(g_commit / (double)QELEMS);
        dout[QELEMS + NQ + 3] = (float)(g_pred / (double)QELEMS);
    }
}

extern "C" void kernel_launch(void* const* d_in, const int* in_sizes, int n_in,
                              void* d_out, int out_size) {
    const float* x     = (const float*)d_in[0];
    const float* emb   = (const float*)d_in[1];
    const float* w_ctx = (const float*)d_in[2];
    const float* w1    = (const float*)d_in[3];
    const float* a1    = (const float*)d_in[4];
    const float* w2    = (const float*)d_in[5];
    const float* a2    = (const float*)d_in[6];
    const float* noise = (const float*)d_in[7];
    const int*   epo   = (n_in > 8) ? (const int*)d_in[8] : nullptr;
    float* dout = (float*)d_out;

    const int SMEM_M1VQ = (33280 + 9216 + 128 + 1024) * 4;   // 174,592 B
    cudaFuncSetAttribute(k_m1vq,   cudaFuncAttributeMaxDynamicSharedMemorySize, SMEM_M1VQ);
    cudaFuncSetAttribute(k_merge2, cudaFuncAttributeMaxDynamicSharedMemorySize, M2_SMEM);

    k_init<<<4, 256>>>();
    k_e2<<<MM / 256, 256>>>(emb);
    k_scale1<<<dim3(8, BB), 256>>>(x);
    k_coef<<<1, 32>>>(epo);
    k_conv<<<dim3(TT / 128, DD / 128, BB), 256>>>(w_ctx, noise, x, dout);
    k_m1vq<<<dim3(TT / 128, BB), 256, SMEM_M1VQ>>>(x, emb, w1, a1, dout);
    k_loss<<<NQ / 8, 256>>>(x, emb, dout);
    k_merge2<<<dim3(TT / 128, BB), 256, M2_SMEM>>>(emb, w2, a2, dout);
    k_stats<<<1, 1024>>>(dout);
    (void)in_sizes; (void)out_size;
}